// round 6
// baseline (speedup 1.0000x reference)
#include <cuda_runtime.h>
#include <math.h>

#define NN 50000
#define EE 1600000
#define HH 128
#define DIN 64
#define DE 16
#define LL 6

// ---------------- scratch (static __device__ globals; no allocation) ----------------
__device__ float g_ha[NN * HH];     // node features (always post-relu)
__device__ float g_msg[NN * HH];    // per-node message linear output
__device__ float g_a2[NN * HH];     // ha + agg (input to update GEMM)
__device__ float g_ssrc[NN];
__device__ float g_sdst[NN];
__device__ float g_sb[(size_t)LL * EE];  // per-layer per-edge bias (CSR order)
__device__ int g_counts[NN];
__device__ int g_rowptr[NN + 1];
__device__ int g_cursor[NN];
__device__ int g_perm[EE];   // csr pos -> original edge id
__device__ int g_srcp[EE];   // csr-ordered src index
__device__ float g_ewp[EE];  // csr-ordered clipped edge weight
__device__ float g_w1p[LL * HH * DE];  // W_e1 * |colsum(W_e2)|
__device__ float g_b1p[LL * HH];       // b_e1 * |colsum(W_e2)|
__device__ float g_sgn[LL * HH];       // sign(colsum(W_e2))
__device__ float g_cas[LL * HH];       // colsum(W_as)
__device__ float g_cad[LL * HH];       // colsum(W_ad)
__device__ float g_be2s[LL];
__device__ float g_bass[LL];
__device__ float g_bads[LL];
__device__ float g_gpart[256 * HH];

// ---------------- init: zero histogram counters ----------------
__global__ void k_init() {
    int i = blockIdx.x * blockDim.x + threadIdx.x;
    if (i < NN) g_counts[i] = 0;
}

// ---------------- precompute column sums / folded edge-MLP weights ----------------
__global__ void k_prep(const float* __restrict__ W_e1, const float* __restrict__ b_e1,
                       const float* __restrict__ W_e2, const float* __restrict__ b_e2,
                       const float* __restrict__ W_as, const float* __restrict__ b_as,
                       const float* __restrict__ W_ad, const float* __restrict__ b_ad) {
    int l = blockIdx.x;       // 0..5
    int t = threadIdx.x;      // 0..127
    const float* was = W_as + l * HH * HH;
    const float* wad = W_ad + l * HH * HH;
    const float* we2 = W_e2 + l * HH * HH;
    float sa = 0.f, sd = 0.f, s2 = 0.f;
    for (int j = 0; j < HH; j++) {
        sa += was[j * HH + t];
        sd += wad[j * HH + t];
        s2 += we2[j * HH + t];
    }
    g_cas[l * HH + t] = sa;
    g_cad[l * HH + t] = sd;
    float a = fabsf(s2);
    g_sgn[l * HH + t] = (s2 >= 0.f) ? 1.f : -1.f;
    g_b1p[l * HH + t] = b_e1[l * HH + t] * a;
    const float* we1 = W_e1 + (l * HH + t) * DE;
    float* w1p = g_w1p + (l * HH + t) * DE;
    for (int k = 0; k < DE; k++) w1p[k] = we1[k] * a;
    if (t == 0) {
        float s = 0.f;
        for (int j = 0; j < HH; j++) s += b_e2[l * HH + j];
        g_be2s[l] = s;
        s = 0.f;
        for (int j = 0; j < HH; j++) s += b_as[l * HH + j];
        g_bass[l] = s;
        s = 0.f;
        for (int j = 0; j < HH; j++) s += b_ad[l * HH + j];
        g_bads[l] = s;
    }
}

// ---------------- CSR build ----------------
__global__ void k_hist(const int* __restrict__ ei) {
    int e = blockIdx.x * blockDim.x + threadIdx.x;
    if (e < EE) atomicAdd(&g_counts[ei[EE + e]], 1);
}

__global__ void k_scan() {
    __shared__ int ss[1024];
    const int CH = 49;  // 1024*49 = 50176 >= NN
    int t = threadIdx.x;
    int s0 = t * CH;
    int s1 = s0 + CH;
    if (s1 > NN) s1 = NN;
    if (s0 > NN) s0 = NN;
    int sum = 0;
    for (int i = s0; i < s1; i++) sum += g_counts[i];
    ss[t] = sum;
    __syncthreads();
    for (int off = 1; off < 1024; off <<= 1) {
        int v = (t >= off) ? ss[t - off] : 0;
        __syncthreads();
        ss[t] += v;
        __syncthreads();
    }
    int run = (t == 0) ? 0 : ss[t - 1];
    for (int i = s0; i < s1; i++) {
        g_rowptr[i] = run;
        g_cursor[i] = run;
        run += g_counts[i];
    }
    if (t == 1023) g_rowptr[NN] = ss[1023];
}

__global__ void k_scatter(const int* __restrict__ ei, const float* __restrict__ ew) {
    int e = blockIdx.x * blockDim.x + threadIdx.x;
    if (e >= EE) return;
    int d = ei[EE + e];
    int pos = atomicAdd(&g_cursor[d], 1);
    g_perm[pos] = e;
    g_srcp[pos] = ei[e];
    float w = ew[e];
    g_ewp[pos] = fminf(fmaxf(w, 0.f), 1.f);
}

// ---------------- per-edge bias for all 6 layers (FMA-bound hot kernel) ----------------
__global__ __launch_bounds__(256) void k_sbias(const float* __restrict__ edge_attr) {
    extern __shared__ float sm[];
    float* sW = sm;              // 12288 floats
    float* sB = sm + 12288;      // 768
    float* sG = sm + 13056;      // 768
    for (int i = threadIdx.x; i < LL * HH * DE; i += 256) sW[i] = g_w1p[i];
    for (int i = threadIdx.x; i < LL * HH; i += 256) {
        sB[i] = g_b1p[i];
        sG[i] = g_sgn[i];
    }
    __syncthreads();
    int p = blockIdx.x * 256 + threadIdx.x;
    if (p >= EE) return;
    int e = g_perm[p];
    const float4* eap = reinterpret_cast<const float4*>(edge_attr + (size_t)e * DE);
    float4 t0 = eap[0], t1 = eap[1], t2 = eap[2], t3 = eap[3];
    t0.x = tanhf(t0.x); t0.y = tanhf(t0.y); t0.z = tanhf(t0.z); t0.w = tanhf(t0.w);
    t1.x = tanhf(t1.x); t1.y = tanhf(t1.y); t1.z = tanhf(t1.z); t1.w = tanhf(t1.w);
    t2.x = tanhf(t2.x); t2.y = tanhf(t2.y); t2.z = tanhf(t2.z); t2.w = tanhf(t2.w);
    t3.x = tanhf(t3.x); t3.y = tanhf(t3.y); t3.z = tanhf(t3.z); t3.w = tanhf(t3.w);
#pragma unroll 1
    for (int l = 0; l < LL; l++) {
        const float4* wl = reinterpret_cast<const float4*>(sW) + l * 512;
        const float* bl = sB + l * HH;
        const float* gl = sG + l * HH;
        float acc0 = 0.f, acc1 = 0.f;
#pragma unroll 4
        for (int j = 0; j < HH; j += 2) {
            {
                float4 w0 = wl[j * 4 + 0], w1 = wl[j * 4 + 1];
                float4 w2 = wl[j * 4 + 2], w3 = wl[j * 4 + 3];
                float xa = fmaf(t0.x, w0.x, bl[j]);
                xa = fmaf(t0.y, w0.y, xa); xa = fmaf(t0.z, w0.z, xa); xa = fmaf(t0.w, w0.w, xa);
                float xb = t1.x * w1.x;
                xb = fmaf(t1.y, w1.y, xb); xb = fmaf(t1.z, w1.z, xb); xb = fmaf(t1.w, w1.w, xb);
                float xc = t2.x * w2.x;
                xc = fmaf(t2.y, w2.y, xc); xc = fmaf(t2.z, w2.z, xc); xc = fmaf(t2.w, w2.w, xc);
                float xd = t3.x * w3.x;
                xd = fmaf(t3.y, w3.y, xd); xd = fmaf(t3.z, w3.z, xd); xd = fmaf(t3.w, w3.w, xd);
                float x = (xa + xb) + (xc + xd);
                acc0 = fmaf(gl[j], fmaxf(x, 0.f), acc0);
            }
            {
                int j1 = j + 1;
                float4 w0 = wl[j1 * 4 + 0], w1 = wl[j1 * 4 + 1];
                float4 w2 = wl[j1 * 4 + 2], w3 = wl[j1 * 4 + 3];
                float xa = fmaf(t0.x, w0.x, bl[j1]);
                xa = fmaf(t0.y, w0.y, xa); xa = fmaf(t0.z, w0.z, xa); xa = fmaf(t0.w, w0.w, xa);
                float xb = t1.x * w1.x;
                xb = fmaf(t1.y, w1.y, xb); xb = fmaf(t1.z, w1.z, xb); xb = fmaf(t1.w, w1.w, xb);
                float xc = t2.x * w2.x;
                xc = fmaf(t2.y, w2.y, xc); xc = fmaf(t2.z, w2.z, xc); xc = fmaf(t2.w, w2.w, xc);
                float xd = t3.x * w3.x;
                xd = fmaf(t3.y, w3.y, xd); xd = fmaf(t3.z, w3.z, xd); xd = fmaf(t3.w, w3.w, xd);
                float x = (xa + xb) + (xc + xd);
                acc1 = fmaf(gl[j1], fmaxf(x, 0.f), acc1);
            }
        }
        g_sb[(size_t)l * EE + p] = acc0 + acc1 + g_be2s[l];
    }
}

// ---------------- tiled fp32 GEMM: C = act(A @ W^T + b), C is [N,128] ----------------
// a_sel: 0=external A, 1=g_ha, 2=g_a2 ; c_sel: 0=g_ha, 1=g_msg
__global__ __launch_bounds__(256, 2) void k_gemm(const float* __restrict__ Aext, int a_sel,
                                                 const float* __restrict__ W,
                                                 const float* __restrict__ bias, int c_sel,
                                                 int nrows, int K, int do_relu) {
    const float* A = (a_sel == 0) ? Aext : (a_sel == 1 ? g_ha : g_a2);
    float* C = (c_sel == 0) ? g_ha : g_msg;

    __shared__ __align__(16) float As[128][33];
    __shared__ __align__(16) float Ws[32][128];

    int tid = threadIdx.x;
    int bm = blockIdx.x * 128;
    int tx = tid & 15;      // 0..15
    int ty = tid >> 4;      // 0..15
    int n0 = tx * 8;
    int m0 = ty * 8;

    float acc[8][8];
#pragma unroll
    for (int i = 0; i < 8; i++)
#pragma unroll
        for (int j = 0; j < 8; j++) acc[i][j] = 0.f;

    int nch = K >> 5;
    for (int ch = 0; ch < nch; ch++) {
        int k0 = ch * 32;
#pragma unroll
        for (int i = 0; i < 4; i++) {
            int idx = tid + i * 256;           // 0..1023
            int m = idx >> 3;
            int kq = (idx & 7) * 4;
            float4 v = make_float4(0.f, 0.f, 0.f, 0.f);
            int gr = bm + m;
            if (gr < nrows)
                v = *reinterpret_cast<const float4*>(A + (size_t)gr * K + k0 + kq);
            As[m][kq] = v.x; As[m][kq + 1] = v.y; As[m][kq + 2] = v.z; As[m][kq + 3] = v.w;
        }
#pragma unroll
        for (int i = 0; i < 4; i++) {
            int idx = tid + i * 256;
            int n = idx >> 3;
            int kq = (idx & 7) * 4;
            float4 v = *reinterpret_cast<const float4*>(W + (size_t)n * K + k0 + kq);
            Ws[kq][n] = v.x; Ws[kq + 1][n] = v.y; Ws[kq + 2][n] = v.z; Ws[kq + 3][n] = v.w;
        }
        __syncthreads();
#pragma unroll 8
        for (int kk = 0; kk < 32; kk++) {
            float a[8];
#pragma unroll
            for (int i = 0; i < 8; i++) a[i] = As[m0 + i][kk];
            float4 b0 = *reinterpret_cast<const float4*>(&Ws[kk][n0]);
            float4 b1 = *reinterpret_cast<const float4*>(&Ws[kk][n0 + 4]);
#pragma unroll
            for (int i = 0; i < 8; i++) {
                acc[i][0] = fmaf(a[i], b0.x, acc[i][0]);
                acc[i][1] = fmaf(a[i], b0.y, acc[i][1]);
                acc[i][2] = fmaf(a[i], b0.z, acc[i][2]);
                acc[i][3] = fmaf(a[i], b0.w, acc[i][3]);
                acc[i][4] = fmaf(a[i], b1.x, acc[i][4]);
                acc[i][5] = fmaf(a[i], b1.y, acc[i][5]);
                acc[i][6] = fmaf(a[i], b1.z, acc[i][6]);
                acc[i][7] = fmaf(a[i], b1.w, acc[i][7]);
            }
        }
        __syncthreads();
    }

    float4 bv0 = *reinterpret_cast<const float4*>(bias + n0);
    float4 bv1 = *reinterpret_cast<const float4*>(bias + n0 + 4);
#pragma unroll
    for (int i = 0; i < 8; i++) {
        int gr = bm + m0 + i;
        if (gr >= nrows) continue;
        float4 o0, o1;
        o0.x = acc[i][0] + bv0.x; o0.y = acc[i][1] + bv0.y;
        o0.z = acc[i][2] + bv0.z; o0.w = acc[i][3] + bv0.w;
        o1.x = acc[i][4] + bv1.x; o1.y = acc[i][5] + bv1.y;
        o1.z = acc[i][6] + bv1.z; o1.w = acc[i][7] + bv1.w;
        if (do_relu) {
            o0.x = fmaxf(o0.x, 0.f); o0.y = fmaxf(o0.y, 0.f);
            o0.z = fmaxf(o0.z, 0.f); o0.w = fmaxf(o0.w, 0.f);
            o1.x = fmaxf(o1.x, 0.f); o1.y = fmaxf(o1.y, 0.f);
            o1.z = fmaxf(o1.z, 0.f); o1.w = fmaxf(o1.w, 0.f);
        }
        float* cp = C + (size_t)gr * HH + n0;
        *reinterpret_cast<float4*>(cp) = o0;
        *reinterpret_cast<float4*>(cp + 4) = o1;
    }
}

// ---------------- per-node attention scores (s_src, s_dst) ----------------
__global__ void k_scores(int l) {
    int gw = (blockIdx.x * blockDim.x + threadIdx.x) >> 5;
    int lane = threadIdx.x & 31;
    if (gw >= NN) return;
    float4 h4 = reinterpret_cast<const float4*>(g_ha)[(size_t)gw * 32 + lane];
    float4 a4 = reinterpret_cast<const float4*>(g_cas + l * HH)[lane];
    float4 d4 = reinterpret_cast<const float4*>(g_cad + l * HH)[lane];
    float vs = h4.x * a4.x + h4.y * a4.y + h4.z * a4.z + h4.w * a4.w;
    float vd = h4.x * d4.x + h4.y * d4.y + h4.z * d4.z + h4.w * d4.w;
#pragma unroll
    for (int off = 16; off; off >>= 1) {
        vs += __shfl_xor_sync(0xffffffffu, vs, off);
        vd += __shfl_xor_sync(0xffffffffu, vd, off);
    }
    if (lane == 0) {
        g_ssrc[gw] = vs + g_bass[l];
        g_sdst[gw] = vd + g_bads[l];
    }
}

// ---------------- gather-aggregate: warp per destination node over CSR ----------------
__global__ void k_agg(int l) {
    int gw = (blockIdx.x * blockDim.x + threadIdx.x) >> 5;
    int lane = threadIdx.x & 31;
    if (gw >= NN) return;
    int n = gw;
    int beg = g_rowptr[n];
    int end = g_rowptr[n + 1];
    float sdn = g_sdst[n];
    const float* __restrict__ sb = g_sb + (size_t)l * EE;
    const float4* __restrict__ msg4 = reinterpret_cast<const float4*>(g_msg);
    float4 acc = make_float4(0.f, 0.f, 0.f, 0.f);
    int p = beg;
    for (; p + 1 < end; p += 2) {
        int s0 = g_srcp[p];
        int s1 = g_srcp[p + 1];
        float x0 = g_ssrc[s0] + sdn + sb[p];
        float x1 = g_ssrc[s1] + sdn + sb[p + 1];
        float gt0 = g_ewp[p] / (1.f + __expf(-x0));
        float gt1 = g_ewp[p + 1] / (1.f + __expf(-x1));
        float4 m0 = msg4[s0 * 32 + lane];
        float4 m1 = msg4[s1 * 32 + lane];
        acc.x = fmaf(m0.x, gt0, acc.x); acc.y = fmaf(m0.y, gt0, acc.y);
        acc.z = fmaf(m0.z, gt0, acc.z); acc.w = fmaf(m0.w, gt0, acc.w);
        acc.x = fmaf(m1.x, gt1, acc.x); acc.y = fmaf(m1.y, gt1, acc.y);
        acc.z = fmaf(m1.z, gt1, acc.z); acc.w = fmaf(m1.w, gt1, acc.w);
    }
    if (p < end) {
        int s0 = g_srcp[p];
        float x0 = g_ssrc[s0] + sdn + sb[p];
        float gt0 = g_ewp[p] / (1.f + __expf(-x0));
        float4 m0 = msg4[s0 * 32 + lane];
        acc.x = fmaf(m0.x, gt0, acc.x); acc.y = fmaf(m0.y, gt0, acc.y);
        acc.z = fmaf(m0.z, gt0, acc.z); acc.w = fmaf(m0.w, gt0, acc.w);
    }
    float4 h4 = reinterpret_cast<const float4*>(g_ha)[(size_t)n * 32 + lane];
    float4 o;
    o.x = h4.x + acc.x; o.y = h4.y + acc.y; o.z = h4.z + acc.z; o.w = h4.w + acc.w;
    reinterpret_cast<float4*>(g_a2)[(size_t)n * 32 + lane] = o;
}

// ---------------- graph readout ----------------
__global__ void k_grep() {
    int c = threadIdx.x & 127;
    int half = threadIdx.x >> 7;
    int rs = blockIdx.x * 196;
    int re = rs + 196;
    if (re > NN) re = NN;
    float acc = 0.f;
    for (int r = rs + half; r < re; r += 2) acc += g_ha[(size_t)r * HH + c];
    __shared__ float sr[256];
    sr[threadIdx.x] = acc;
    __syncthreads();
    if (threadIdx.x < 128)
        g_gpart[blockIdx.x * HH + threadIdx.x] = sr[threadIdx.x] + sr[threadIdx.x + 128];
}

__global__ void k_final(const float* __restrict__ W_out, const float* __restrict__ b_out,
                        float* __restrict__ out) {
    int t = threadIdx.x;  // 128 threads
    float s = 0.f;
    for (int b = 0; b < 256; b++) s += g_gpart[b * HH + t];
    float v = s * (1.f / (float)NN) * W_out[t];
    __shared__ float r[128];
    r[t] = v;
    __syncthreads();
    for (int off = 64; off; off >>= 1) {
        if (t < off) r[t] += r[t + off];
        __syncthreads();
    }
    if (t == 0) out[0] = (r[0] + b_out[0]) * (1.f / 50.f);
}

// ---------------- launch ----------------
extern "C" void kernel_launch(void* const* d_in, const int* in_sizes, int n_in,
                              void* d_out, int out_size) {
    const float* x      = (const float*)d_in[0];
    const int*   ei     = (const int*)d_in[1];
    const float* ew     = (const float*)d_in[2];
    const float* ea     = (const float*)d_in[3];
    const float* W_in   = (const float*)d_in[4];
    const float* b_in   = (const float*)d_in[5];
    const float* W_e1   = (const float*)d_in[6];
    const float* b_e1   = (const float*)d_in[7];
    const float* W_e2   = (const float*)d_in[8];
    const float* b_e2   = (const float*)d_in[9];
    const float* W_as   = (const float*)d_in[10];
    const float* b_as   = (const float*)d_in[11];
    const float* W_ad   = (const float*)d_in[12];
    const float* b_ad   = (const float*)d_in[13];
    const float* W_m    = (const float*)d_in[14];
    const float* b_m    = (const float*)d_in[15];
    const float* W_r    = (const float*)d_in[16];
    const float* b_r    = (const float*)d_in[17];
    const float* W_out  = (const float*)d_in[18];
    const float* b_out  = (const float*)d_in[19];
    float* out = (float*)d_out;

    cudaFuncSetAttribute(k_sbias, cudaFuncAttributeMaxDynamicSharedMemorySize, 55296);

    const int gridE = (EE + 255) / 256;   // 6250
    const int gridN = (NN + 255) / 256;   // 196
    const int gridG = (NN + 127) / 128;   // 391

    k_init<<<gridN, 256>>>();
    k_prep<<<LL, HH>>>(W_e1, b_e1, W_e2, b_e2, W_as, b_as, W_ad, b_ad);
    k_hist<<<gridE, 256>>>(ei);
    k_scan<<<1, 1024>>>();
    k_scatter<<<gridE, 256>>>(ei, ew);
    // input projection: ha = relu(x @ W_in^T + b_in)
    k_gemm<<<gridG, 256>>>(x, 0, W_in, b_in, 0, NN, DIN, 1);
    // per-edge bias for all 6 layers (CSR order)
    k_sbias<<<gridE, 256, 55296>>>(ea);

    for (int l = 0; l < LL; l++) {
        k_scores<<<gridE, 256>>>(l);
        // msg = ha @ W_m^T + b_m
        k_gemm<<<gridG, 256>>>(nullptr, 1, W_m + l * HH * HH, b_m + l * HH, 1, NN, HH, 0);
        // a2 = ha + segment_sum(msg[src] * gate)
        k_agg<<<gridE, 256>>>(l);
        // ha = relu(a2 @ W_r^T + b_r)
        k_gemm<<<gridG, 256>>>(nullptr, 2, W_r + l * HH * HH, b_r + l * HH, 0, NN, HH, 1);
    }

    k_grep<<<256, 256>>>();
    k_final<<<1, 128>>>(W_out, b_out, out);
}

// round 9
// speedup vs baseline: 1.4814x; 1.4814x over previous
#include <cuda_runtime.h>
#include <cuda_bf16.h>
#include <math.h>
#include <stdint.h>

#define NN 50000
#define EE 1600000
#define HH 128
#define DIN 64
#define DE 16
#define LL 6

// ---------------- scratch (static __device__ globals; no allocation) ----------------
__device__ float g_ha[NN * HH];     // node features (always post-relu)
__device__ float g_msg[NN * HH];    // per-node message linear output
__device__ float g_a2[NN * HH];     // ha + agg (input to update GEMM)
__device__ float g_ssrc[NN];
__device__ float g_sdst[NN];
__device__ float g_sb[(size_t)LL * EE];  // per-layer per-edge bias (CSR order)
__device__ int g_counts[NN];
__device__ int g_rowptr[NN + 1];
__device__ int g_cursor[NN];
__device__ int g_perm[EE];   // csr pos -> original edge id
__device__ int g_srcp[EE];   // csr-ordered src index
__device__ float g_ewp[EE];  // csr-ordered clipped edge weight
__device__ float g_w1p[LL * HH * DE];  // W_e1 * colsum(W_e2)  (SIGNED fold)
__device__ float g_b1p[LL * HH];       // b_e1 * colsum(W_e2)
__device__ float g_sgnF[LL * HH];      // sign(colsum(W_e2)) as +-1.0f
__device__ float g_cas[LL * HH];       // colsum(W_as)
__device__ float g_cad[LL * HH];       // colsum(W_ad)
__device__ float g_be2s[LL];
__device__ float g_bass[LL];
__device__ float g_bads[LL];
__device__ float g_gpart[256 * HH];
__device__ int g_bsum[49];
__device__ int g_boff[49];
// pre-packed B fragments for mma.sync: [l][ntile][lane] -> {b0_hi, b1_hi, b0_lo, b1_lo}
__device__ __align__(16) uint4 g_Bfrag[LL * 16 * 32];

// ---------------- small helpers ----------------
__device__ __forceinline__ float tanh_fast(float x) {
    float y;
    asm("tanh.approx.f32 %0, %1;" : "=f"(y) : "f"(x));
    return y;
}
__device__ __forceinline__ unsigned pk2(float a, float b) {
    __nv_bfloat162 t = __floats2bfloat162_rn(a, b);
    return *reinterpret_cast<unsigned*>(&t);
}
__device__ __forceinline__ float hif(float a) {
    return __bfloat162float(__float2bfloat16(a));
}
__device__ __forceinline__ void mma16816(float& d0, float& d1, float& d2, float& d3,
                                         unsigned a0, unsigned a1, unsigned a2, unsigned a3,
                                         unsigned b0, unsigned b1,
                                         float c0, float c1, float c2, float c3) {
    asm volatile(
        "mma.sync.aligned.m16n8k16.row.col.f32.bf16.bf16.f32 "
        "{%0,%1,%2,%3}, {%4,%5,%6,%7}, {%8,%9}, {%10,%11,%12,%13};"
        : "=f"(d0), "=f"(d1), "=f"(d2), "=f"(d3)
        : "r"(a0), "r"(a1), "r"(a2), "r"(a3), "r"(b0), "r"(b1),
          "f"(c0), "f"(c1), "f"(c2), "f"(c3));
}

// ---------------- init: zero histogram counters ----------------
__global__ void k_init() {
    int i = blockIdx.x * blockDim.x + threadIdx.x;
    if (i < NN) g_counts[i] = 0;
}

// ---------------- precompute column sums / folded edge-MLP weights ----------------
__global__ void k_prep(const float* __restrict__ W_e1, const float* __restrict__ b_e1,
                       const float* __restrict__ W_e2, const float* __restrict__ b_e2,
                       const float* __restrict__ W_as, const float* __restrict__ b_as,
                       const float* __restrict__ W_ad, const float* __restrict__ b_ad) {
    int l = blockIdx.x;       // 0..5
    int t = threadIdx.x;      // 0..127
    const float* was = W_as + l * HH * HH;
    const float* wad = W_ad + l * HH * HH;
    const float* we2 = W_e2 + l * HH * HH;
    float sa = 0.f, sd = 0.f, s2 = 0.f;
    for (int j = 0; j < HH; j++) {
        sa += was[j * HH + t];
        sd += wad[j * HH + t];
        s2 += we2[j * HH + t];
    }
    g_cas[l * HH + t] = sa;
    g_cad[l * HH + t] = sd;
    // SIGNED fold: x_unit = colsum * (W_e1 . t + b_e1); contribution = s*max(s*x,0)
    g_b1p[l * HH + t] = b_e1[l * HH + t] * s2;
    g_sgnF[l * HH + t] = (s2 < 0.f) ? -1.f : 1.f;
    const float* we1 = W_e1 + (l * HH + t) * DE;
    float* w1p = g_w1p + (l * HH + t) * DE;
    for (int k = 0; k < DE; k++) w1p[k] = we1[k] * s2;
    if (t == 0) {
        float s = 0.f;
        for (int j = 0; j < HH; j++) s += b_e2[l * HH + j];
        g_be2s[l] = s;
        s = 0.f;
        for (int j = 0; j < HH; j++) s += b_as[l * HH + j];
        g_bass[l] = s;
        s = 0.f;
        for (int j = 0; j < HH; j++) s += b_ad[l * HH + j];
        g_bads[l] = s;
    }
}

// ---------------- pre-pack B fragments for mma.sync ----------------
// m16n8k16 B fragment (K x N col layout): thread lane holds col n = lane/4,
// k pairs (lane%4)*2+{0,1} in b0 and (lane%4)*2+8+{0,1} in b1.
__global__ void k_prepB() {
    int l = blockIdx.x >> 4;       // 0..5
    int nt = blockIdx.x & 15;      // 0..15
    int lane = threadIdx.x;        // 0..31
    int n = nt * 8 + (lane >> 2);
    int k0 = (lane & 3) * 2;
    const float* w = g_w1p + (l * HH + n) * DE;
    float w0 = w[k0], w1 = w[k0 + 1], w8 = w[k0 + 8], w9 = w[k0 + 9];
    float h0 = hif(w0), h1 = hif(w1), h8 = hif(w8), h9 = hif(w9);
    uint4 f;
    f.x = pk2(h0, h1);            // b0 hi
    f.y = pk2(h8, h9);            // b1 hi
    f.z = pk2(w0 - h0, w1 - h1);  // b0 lo
    f.w = pk2(w8 - h8, w9 - h9);  // b1 lo
    g_Bfrag[(l * 16 + nt) * 32 + lane] = f;
}

// ---------------- CSR build ----------------
__global__ void k_hist(const int* __restrict__ ei) {
    int e = blockIdx.x * blockDim.x + threadIdx.x;
    if (e < EE) atomicAdd(&g_counts[ei[EE + e]], 1);
}

__global__ void k_scanA() {
    __shared__ int sh[1024];
    int i = blockIdx.x * 1024 + threadIdx.x;
    int v = (i < NN) ? g_counts[i] : 0;
    sh[threadIdx.x] = v;
    __syncthreads();
    for (int off = 512; off > 0; off >>= 1) {
        if (threadIdx.x < off) sh[threadIdx.x] += sh[threadIdx.x + off];
        __syncthreads();
    }
    if (threadIdx.x == 0) g_bsum[blockIdx.x] = sh[0];
}
__global__ void k_scanB() {
    if (threadIdx.x == 0) {
        int r = 0;
        for (int b = 0; b < 49; b++) { g_boff[b] = r; r += g_bsum[b]; }
    }
}
__global__ void k_scanC() {
    __shared__ int sh[1024];
    int t = threadIdx.x;
    int i = blockIdx.x * 1024 + t;
    int v = (i < NN) ? g_counts[i] : 0;
    sh[t] = v;
    __syncthreads();
    for (int off = 1; off < 1024; off <<= 1) {
        int x = (t >= off) ? sh[t - off] : 0;
        __syncthreads();
        sh[t] += x;
        __syncthreads();
    }
    if (i < NN) {
        int excl = sh[t] - v + g_boff[blockIdx.x];
        g_rowptr[i] = excl;
        g_cursor[i] = excl;
        if (i == NN - 1) g_rowptr[NN] = excl + v;
    }
}

__global__ void k_scatter(const int* __restrict__ ei, const float* __restrict__ ew) {
    int e = blockIdx.x * blockDim.x + threadIdx.x;
    if (e >= EE) return;
    int d = ei[EE + e];
    int pos = atomicAdd(&g_cursor[d], 1);
    g_perm[pos] = e;
    g_srcp[pos] = ei[e];
    float w = ew[e];
    g_ewp[pos] = fminf(fmaxf(w, 0.f), 1.f);
}

// ---------------- per-edge bias for all 6 layers via mma.sync bf16 ----------------
// 256 threads = 8 warps; warp handles 16 CSR edge rows. CTA tile = 128 edges.
// smem: B fragments 48KB + bias 3KB + sign 3KB = 54KB.
#define SBT_SMEM (49152 + 3072 + 3072)
__global__ __launch_bounds__(256) void k_sbias_tc(const float* __restrict__ ea) {
    extern __shared__ char smem[];
    uint4* sF = reinterpret_cast<uint4*>(smem);                  // [l*16+nt][lane]
    float* sB = reinterpret_cast<float*>(smem + 49152);          // [l][128]
    float* sS = reinterpret_cast<float*>(smem + 49152 + 3072);   // [l][128]
    for (int i = threadIdx.x; i < 3072; i += 256) sF[i] = g_Bfrag[i];
    for (int i = threadIdx.x; i < 768; i += 256) {
        sB[i] = g_b1p[i];
        sS[i] = g_sgnF[i];
    }
    __syncthreads();

    const int wid = threadIdx.x >> 5;
    const int lane = threadIdx.x & 31;
    const int rA = lane >> 2;   // fragment row group 0..7
    const int qq = lane & 3;    // col-pair / k-pair id

    for (int tile = blockIdx.x; tile < EE / 128; tile += gridDim.x) {
        const int p0 = tile * 128 + wid * 16;
        // ---- build A fragments in registers (rows rA and rA+8 of the 16-edge tile)
        unsigned ah[4], al[4];
        {
            int e0 = g_perm[p0 + rA];
            int e1 = g_perm[p0 + rA + 8];
            const float2* r0 = reinterpret_cast<const float2*>(ea + (size_t)e0 * DE);
            const float2* r1 = reinterpret_cast<const float2*>(ea + (size_t)e1 * DE);
            float2 x0 = r0[qq], x2 = r0[qq + 4];
            float2 y0 = r1[qq], y2 = r1[qq + 4];
            x0.x = tanh_fast(x0.x); x0.y = tanh_fast(x0.y);
            x2.x = tanh_fast(x2.x); x2.y = tanh_fast(x2.y);
            y0.x = tanh_fast(y0.x); y0.y = tanh_fast(y0.y);
            y2.x = tanh_fast(y2.x); y2.y = tanh_fast(y2.y);
            float hx0 = hif(x0.x), hx1 = hif(x0.y);
            float hx8 = hif(x2.x), hx9 = hif(x2.y);
            float hy0 = hif(y0.x), hy1 = hif(y0.y);
            float hy8 = hif(y2.x), hy9 = hif(y2.y);
            ah[0] = pk2(hx0, hx1);               // row rA,   k qq*2
            ah[1] = pk2(hy0, hy1);               // row rA+8, k qq*2
            ah[2] = pk2(hx8, hx9);               // row rA,   k qq*2+8
            ah[3] = pk2(hy8, hy9);               // row rA+8, k qq*2+8
            al[0] = pk2(x0.x - hx0, x0.y - hx1);
            al[1] = pk2(y0.x - hy0, y0.y - hy1);
            al[2] = pk2(x2.x - hx8, x2.y - hx9);
            al[3] = pk2(y2.x - hy8, y2.y - hy9);
        }
        // ---- 6 layers: 16 n-tiles x 3 compensated mma each, epilogue in regs
#pragma unroll 1
        for (int l = 0; l < LL; l++) {
            const float* bl = sB + l * HH;
            const float* sl = sS + l * HH;
            float accA = 0.f, accB = 0.f;
#pragma unroll
            for (int nt = 0; nt < 16; nt++) {
                uint4 bf = sF[(l * 16 + nt) * 32 + lane];
                float2 bb = *reinterpret_cast<const float2*>(bl + nt * 8 + qq * 2);
                float d0 = bb.x, d1 = bb.y, d2 = bb.x, d3 = bb.y;  // bias init (per col)
                mma16816(d0, d1, d2, d3, ah[0], ah[1], ah[2], ah[3], bf.x, bf.y,
                         d0, d1, d2, d3);
                mma16816(d0, d1, d2, d3, al[0], al[1], al[2], al[3], bf.x, bf.y,
                         d0, d1, d2, d3);
                mma16816(d0, d1, d2, d3, ah[0], ah[1], ah[2], ah[3], bf.z, bf.w,
                         d0, d1, d2, d3);
                float2 ss = *reinterpret_cast<const float2*>(sl + nt * 8 + qq * 2);
                // contribution of unit u: s*max(s*x,0)  (== max(x,0) or min(x,0))
                accA = fmaf(fmaxf(d0 * ss.x, 0.f), ss.x, accA);
                accA = fmaf(fmaxf(d1 * ss.y, 0.f), ss.y, accA);
                accB = fmaf(fmaxf(d2 * ss.x, 0.f), ss.x, accB);
                accB = fmaf(fmaxf(d3 * ss.y, 0.f), ss.y, accB);
            }
            accA += __shfl_xor_sync(0xffffffffu, accA, 1);
            accA += __shfl_xor_sync(0xffffffffu, accA, 2);
            accB += __shfl_xor_sync(0xffffffffu, accB, 1);
            accB += __shfl_xor_sync(0xffffffffu, accB, 2);
            if (qq == 0) {
                float c = g_be2s[l];
                g_sb[(size_t)l * EE + p0 + rA] = accA + c;
                g_sb[(size_t)l * EE + p0 + rA + 8] = accB + c;
            }
        }
    }
}

// ---------------- tiled fp32 GEMM: C = act(A @ W^T + b), C is [N,128] ----------------
// a_sel: 0=external A, 1=g_ha, 2=g_a2 ; c_sel: 0=g_ha, 1=g_msg
__global__ __launch_bounds__(256, 2) void k_gemm(const float* __restrict__ Aext, int a_sel,
                                                 const float* __restrict__ W,
                                                 const float* __restrict__ bias, int c_sel,
                                                 int nrows, int K, int do_relu) {
    const float* A = (a_sel == 0) ? Aext : (a_sel == 1 ? g_ha : g_a2);
    float* C = (c_sel == 0) ? g_ha : g_msg;

    __shared__ __align__(16) float As[128][33];
    __shared__ __align__(16) float Ws[32][128];

    int tid = threadIdx.x;
    int bm = blockIdx.x * 128;
    int tx = tid & 15;
    int ty = tid >> 4;
    int n0 = tx * 8;
    int m0 = ty * 8;

    float acc[8][8];
#pragma unroll
    for (int i = 0; i < 8; i++)
#pragma unroll
        for (int j = 0; j < 8; j++) acc[i][j] = 0.f;

    int nch = K >> 5;
    for (int ch = 0; ch < nch; ch++) {
        int k0 = ch * 32;
#pragma unroll
        for (int i = 0; i < 4; i++) {
            int idx = tid + i * 256;
            int m = idx >> 3;
            int kq = (idx & 7) * 4;
            float4 v = make_float4(0.f, 0.f, 0.f, 0.f);
            int gr = bm + m;
            if (gr < nrows)
                v = *reinterpret_cast<const float4*>(A + (size_t)gr * K + k0 + kq);
            As[m][kq] = v.x; As[m][kq + 1] = v.y; As[m][kq + 2] = v.z; As[m][kq + 3] = v.w;
        }
#pragma unroll
        for (int i = 0; i < 4; i++) {
            int idx = tid + i * 256;
            int n = idx >> 3;
            int kq = (idx & 7) * 4;
            float4 v = *reinterpret_cast<const float4*>(W + (size_t)n * K + k0 + kq);
            Ws[kq][n] = v.x; Ws[kq + 1][n] = v.y; Ws[kq + 2][n] = v.z; Ws[kq + 3][n] = v.w;
        }
        __syncthreads();
#pragma unroll 8
        for (int kk = 0; kk < 32; kk++) {
            float a[8];
#pragma unroll
            for (int i = 0; i < 8; i++) a[i] = As[m0 + i][kk];
            float4 b0 = *reinterpret_cast<const float4*>(&Ws[kk][n0]);
            float4 b1 = *reinterpret_cast<const float4*>(&Ws[kk][n0 + 4]);
#pragma unroll
            for (int i = 0; i < 8; i++) {
                acc[i][0] = fmaf(a[i], b0.x, acc[i][0]);
                acc[i][1] = fmaf(a[i], b0.y, acc[i][1]);
                acc[i][2] = fmaf(a[i], b0.z, acc[i][2]);
                acc[i][3] = fmaf(a[i], b0.w, acc[i][3]);
                acc[i][4] = fmaf(a[i], b1.x, acc[i][4]);
                acc[i][5] = fmaf(a[i], b1.y, acc[i][5]);
                acc[i][6] = fmaf(a[i], b1.z, acc[i][6]);
                acc[i][7] = fmaf(a[i], b1.w, acc[i][7]);
            }
        }
        __syncthreads();
    }

    float4 bv0 = *reinterpret_cast<const float4*>(bias + n0);
    float4 bv1 = *reinterpret_cast<const float4*>(bias + n0 + 4);
#pragma unroll
    for (int i = 0; i < 8; i++) {
        int gr = bm + m0 + i;
        if (gr >= nrows) continue;
        float4 o0, o1;
        o0.x = acc[i][0] + bv0.x; o0.y = acc[i][1] + bv0.y;
        o0.z = acc[i][2] + bv0.z; o0.w = acc[i][3] + bv0.w;
        o1.x = acc[i][4] + bv1.x; o1.y = acc[i][5] + bv1.y;
        o1.z = acc[i][6] + bv1.z; o1.w = acc[i][7] + bv1.w;
        if (do_relu) {
            o0.x = fmaxf(o0.x, 0.f); o0.y = fmaxf(o0.y, 0.f);
            o0.z = fmaxf(o0.z, 0.f); o0.w = fmaxf(o0.w, 0.f);
            o1.x = fmaxf(o1.x, 0.f); o1.y = fmaxf(o1.y, 0.f);
            o1.z = fmaxf(o1.z, 0.f); o1.w = fmaxf(o1.w, 0.f);
        }
        float* cp = C + (size_t)gr * HH + n0;
        *reinterpret_cast<float4*>(cp) = o0;
        *reinterpret_cast<float4*>(cp + 4) = o1;
    }
}

// ---------------- per-node attention scores (s_src, s_dst) ----------------
__global__ void k_scores(int l) {
    int gw = (blockIdx.x * blockDim.x + threadIdx.x) >> 5;
    int lane = threadIdx.x & 31;
    if (gw >= NN) return;
    float4 h4 = reinterpret_cast<const float4*>(g_ha)[(size_t)gw * 32 + lane];
    float4 a4 = reinterpret_cast<const float4*>(g_cas + l * HH)[lane];
    float4 d4 = reinterpret_cast<const float4*>(g_cad + l * HH)[lane];
    float vs = h4.x * a4.x + h4.y * a4.y + h4.z * a4.z + h4.w * a4.w;
    float vd = h4.x * d4.x + h4.y * d4.y + h4.z * d4.z + h4.w * d4.w;
#pragma unroll
    for (int off = 16; off; off >>= 1) {
        vs += __shfl_xor_sync(0xffffffffu, vs, off);
        vd += __shfl_xor_sync(0xffffffffu, vd, off);
    }
    if (lane == 0) {
        g_ssrc[gw] = vs + g_bass[l];
        g_sdst[gw] = vd + g_bads[l];
    }
}

// ---------------- gather-aggregate: warp per destination node over CSR ----------------
__global__ void k_agg(int l) {
    int gw = (blockIdx.x * blockDim.x + threadIdx.x) >> 5;
    int lane = threadIdx.x & 31;
    if (gw >= NN) return;
    int n = gw;
    int beg = g_rowptr[n];
    int end = g_rowptr[n + 1];
    float sdn = g_sdst[n];
    const float* __restrict__ sb = g_sb + (size_t)l * EE;
    const float4* __restrict__ msg4 = reinterpret_cast<const float4*>(g_msg);
    float4 acc = make_float4(0.f, 0.f, 0.f, 0.f);
    int p = beg;
    for (; p + 1 < end; p += 2) {
        int s0 = g_srcp[p];
        int s1 = g_srcp[p + 1];
        float x0 = g_ssrc[s0] + sdn + sb[p];
        float x1 = g_ssrc[s1] + sdn + sb[p + 1];
        float gt0 = g_ewp[p] / (1.f + __expf(-x0));
        float gt1 = g_ewp[p + 1] / (1.f + __expf(-x1));
        float4 m0 = msg4[s0 * 32 + lane];
        float4 m1 = msg4[s1 * 32 + lane];
        acc.x = fmaf(m0.x, gt0, acc.x); acc.y = fmaf(m0.y, gt0, acc.y);
        acc.z = fmaf(m0.z, gt0, acc.z); acc.w = fmaf(m0.w, gt0, acc.w);
        acc.x = fmaf(m1.x, gt1, acc.x); acc.y = fmaf(m1.y, gt1, acc.y);
        acc.z = fmaf(m1.z, gt1, acc.z); acc.w = fmaf(m1.w, gt1, acc.w);
    }
    if (p < end) {
        int s0 = g_srcp[p];
        float x0 = g_ssrc[s0] + sdn + sb[p];
        float gt0 = g_ewp[p] / (1.f + __expf(-x0));
        float4 m0 = msg4[s0 * 32 + lane];
        acc.x = fmaf(m0.x, gt0, acc.x); acc.y = fmaf(m0.y, gt0, acc.y);
        acc.z = fmaf(m0.z, gt0, acc.z); acc.w = fmaf(m0.w, gt0, acc.w);
    }
    float4 h4 = reinterpret_cast<const float4*>(g_ha)[(size_t)n * 32 + lane];
    float4 o;
    o.x = h4.x + acc.x; o.y = h4.y + acc.y; o.z = h4.z + acc.z; o.w = h4.w + acc.w;
    reinterpret_cast<float4*>(g_a2)[(size_t)n * 32 + lane] = o;
}

// ---------------- graph readout ----------------
__global__ void k_grep() {
    int c = threadIdx.x & 127;
    int half = threadIdx.x >> 7;
    int rs = blockIdx.x * 196;
    int re = rs + 196;
    if (re > NN) re = NN;
    float acc = 0.f;
    for (int r = rs + half; r < re; r += 2) acc += g_ha[(size_t)r * HH + c];
    __shared__ float sr[256];
    sr[threadIdx.x] = acc;
    __syncthreads();
    if (threadIdx.x < 128)
        g_gpart[blockIdx.x * HH + threadIdx.x] = sr[threadIdx.x] + sr[threadIdx.x + 128];
}

__global__ void k_final(const float* __restrict__ W_out, const float* __restrict__ b_out,
                        float* __restrict__ out) {
    int t = threadIdx.x;  // 128 threads
    float s = 0.f;
    for (int b = 0; b < 256; b++) s += g_gpart[b * HH + t];
    float v = s * (1.f / (float)NN) * W_out[t];
    __shared__ float r[128];
    r[t] = v;
    __syncthreads();
    for (int off = 64; off; off >>= 1) {
        if (t < off) r[t] += r[t + off];
        __syncthreads();
    }
    if (t == 0) out[0] = (r[0] + b_out[0]) * (1.f / 50.f);
}

// ---------------- launch ----------------
extern "C" void kernel_launch(void* const* d_in, const int* in_sizes, int n_in,
                              void* d_out, int out_size) {
    const float* x      = (const float*)d_in[0];
    const int*   ei     = (const int*)d_in[1];
    const float* ew     = (const float*)d_in[2];
    const float* ea     = (const float*)d_in[3];
    const float* W_in   = (const float*)d_in[4];
    const float* b_in   = (const float*)d_in[5];
    const float* W_e1   = (const float*)d_in[6];
    const float* b_e1   = (const float*)d_in[7];
    const float* W_e2   = (const float*)d_in[8];
    const float* b_e2   = (const float*)d_in[9];
    const float* W_as   = (const float*)d_in[10];
    const float* b_as   = (const float*)d_in[11];
    const float* W_ad   = (const float*)d_in[12];
    const float* b_ad   = (const float*)d_in[13];
    const float* W_m    = (const float*)d_in[14];
    const float* b_m    = (const float*)d_in[15];
    const float* W_r    = (const float*)d_in[16];
    const float* b_r    = (const float*)d_in[17];
    const float* W_out  = (const float*)d_in[18];
    const float* b_out  = (const float*)d_in[19];
    float* out = (float*)d_out;

    cudaFuncSetAttribute(k_sbias_tc, cudaFuncAttributeMaxDynamicSharedMemorySize, SBT_SMEM);

    const int gridE = (EE + 255) / 256;   // 6250
    const int gridN = (NN + 255) / 256;   // 196
    const int gridG = (NN + 127) / 128;   // 391

    k_init<<<gridN, 256>>>();
    k_prep<<<LL, HH>>>(W_e1, b_e1, W_e2, b_e2, W_as, b_as, W_ad, b_ad);
    k_prepB<<<LL * 16, 32>>>();
    k_hist<<<gridE, 256>>>(ei);
    k_scanA<<<49, 1024>>>();
    k_scanB<<<1, 32>>>();
    k_scanC<<<49, 1024>>>();
    k_scatter<<<gridE, 256>>>(ei, ew);
    // input projection: ha = relu(x @ W_in^T + b_in)
    k_gemm<<<gridG, 256>>>(x, 0, W_in, b_in, 0, NN, DIN, 1);
    // per-edge bias for all 6 layers (CSR order), tensor cores via mma.sync
    k_sbias_tc<<<625, 256, SBT_SMEM>>>(ea);

    for (int l = 0; l < LL; l++) {
        k_scores<<<gridE, 256>>>(l);
        // msg = ha @ W_m^T + b_m
        k_gemm<<<gridG, 256>>>(nullptr, 1, W_m + l * HH * HH, b_m + l * HH, 1, NN, HH, 0);
        // a2 = ha + segment_sum(msg[src] * gate)
        k_agg<<<gridE, 256>>>(l);
        // ha = relu(a2 @ W_r^T + b_r)
        k_gemm<<<gridG, 256>>>(nullptr, 2, W_r + l * HH * HH, b_r + l * HH, 0, NN, HH, 1);
    }

    k_grep<<<256, 256>>>();
    k_final<<<1, 128>>>(W_out, b_out, out);
}

// round 12
// speedup vs baseline: 1.7306x; 1.1682x over previous
#include <cuda_runtime.h>
#include <cuda_bf16.h>
#include <math.h>
#include <stdint.h>

#define NN 50000
#define EE 1600000
#define HH 128
#define DIN 64
#define DE 16
#define LL 6

// ---------------- scratch (static __device__ globals; no allocation) ----------------
__device__ float g_ha[NN * HH];     // node features (always post-relu)
__device__ float g_msg[NN * HH];    // per-node message linear output
__device__ float g_a2[NN * HH];     // ha + agg (input to update GEMM)
__device__ float g_ssrc[NN];
__device__ float g_sdst[NN];
__device__ float g_sb[(size_t)LL * EE];  // per-layer per-edge bias (CSR order)
__device__ int g_counts[NN];
__device__ int g_rowptr[NN + 1];
__device__ int g_cursor[NN];
__device__ int g_perm[EE];   // csr pos -> original edge id
__device__ int g_srcp[EE];   // csr-ordered src index
__device__ float g_ewp[EE];  // csr-ordered clipped edge weight
__device__ float g_w1p[LL * HH * DE];  // W_e1 * colsum(W_e2)  (SIGNED fold)
__device__ float g_b1p[LL * HH];       // b_e1 * colsum(W_e2)
__device__ float g_sgnF[LL * HH];      // sign(colsum(W_e2)) as +-1.0f
__device__ float g_cas[LL * HH];       // colsum(W_as)
__device__ float g_cad[LL * HH];       // colsum(W_ad)
__device__ float g_be2s[LL];
__device__ float g_bass[LL];
__device__ float g_bads[LL];
__device__ float g_gpart[256 * HH];
__device__ int g_bsum[49];
__device__ int g_boff[49];
// pre-packed B fragments for edge-MLP mma: [l][ntile][lane] -> {b0_hi, b1_hi, b0_lo, b1_lo}
__device__ __align__(16) uint4 g_Bfrag[LL * 16 * 32];
// pre-packed W fragments for node GEMMs: 12 matrices (l*2: W_m, l*2+1: W_r), each
// [ks 0..7][nt 0..15][lane 0..31] -> {b0_hi, b1_hi, b0_lo, b1_lo}
__device__ __align__(16) uint4 g_Wfrag[12 * 4096];

// ---------------- small helpers ----------------
__device__ __forceinline__ float tanh_fast(float x) {
    float y;
    asm("tanh.approx.f32 %0, %1;" : "=f"(y) : "f"(x));
    return y;
}
__device__ __forceinline__ unsigned pk2(float a, float b) {
    __nv_bfloat162 t = __floats2bfloat162_rn(a, b);
    return *reinterpret_cast<unsigned*>(&t);
}
__device__ __forceinline__ float hif(float a) {
    return __bfloat162float(__float2bfloat16(a));
}
__device__ __forceinline__ void mma16816(float& d0, float& d1, float& d2, float& d3,
                                         unsigned a0, unsigned a1, unsigned a2, unsigned a3,
                                         unsigned b0, unsigned b1,
                                         float c0, float c1, float c2, float c3) {
    asm volatile(
        "mma.sync.aligned.m16n8k16.row.col.f32.bf16.bf16.f32 "
        "{%0,%1,%2,%3}, {%4,%5,%6,%7}, {%8,%9}, {%10,%11,%12,%13};"
        : "=f"(d0), "=f"(d1), "=f"(d2), "=f"(d3)
        : "r"(a0), "r"(a1), "r"(a2), "r"(a3), "r"(b0), "r"(b1),
          "f"(c0), "f"(c1), "f"(c2), "f"(c3));
}

// ---------------- init: zero histogram counters ----------------
__global__ void k_init() {
    int i = blockIdx.x * blockDim.x + threadIdx.x;
    if (i < NN) g_counts[i] = 0;
}

// ---------------- precompute column sums / folded edge-MLP weights ----------------
__global__ void k_prep(const float* __restrict__ W_e1, const float* __restrict__ b_e1,
                       const float* __restrict__ W_e2, const float* __restrict__ b_e2,
                       const float* __restrict__ W_as, const float* __restrict__ b_as,
                       const float* __restrict__ W_ad, const float* __restrict__ b_ad) {
    int l = blockIdx.x;       // 0..5
    int t = threadIdx.x;      // 0..127
    const float* was = W_as + l * HH * HH;
    const float* wad = W_ad + l * HH * HH;
    const float* we2 = W_e2 + l * HH * HH;
    float sa = 0.f, sd = 0.f, s2 = 0.f;
    for (int j = 0; j < HH; j++) {
        sa += was[j * HH + t];
        sd += wad[j * HH + t];
        s2 += we2[j * HH + t];
    }
    g_cas[l * HH + t] = sa;
    g_cad[l * HH + t] = sd;
    // SIGNED fold: x_unit = colsum * (W_e1 . t + b_e1); contribution = s*max(s*x,0)
    g_b1p[l * HH + t] = b_e1[l * HH + t] * s2;
    g_sgnF[l * HH + t] = (s2 < 0.f) ? -1.f : 1.f;
    const float* we1 = W_e1 + (l * HH + t) * DE;
    float* w1p = g_w1p + (l * HH + t) * DE;
    for (int k = 0; k < DE; k++) w1p[k] = we1[k] * s2;
    if (t == 0) {
        float s = 0.f;
        for (int j = 0; j < HH; j++) s += b_e2[l * HH + j];
        g_be2s[l] = s;
        s = 0.f;
        for (int j = 0; j < HH; j++) s += b_as[l * HH + j];
        g_bass[l] = s;
        s = 0.f;
        for (int j = 0; j < HH; j++) s += b_ad[l * HH + j];
        g_bads[l] = s;
    }
}

// ---------------- pre-pack B fragments (edge MLP, K=16) ----------------
__global__ void k_prepB() {
    int l = blockIdx.x >> 4;       // 0..5
    int nt = blockIdx.x & 15;      // 0..15
    int lane = threadIdx.x;        // 0..31
    int n = nt * 8 + (lane >> 2);
    int k0 = (lane & 3) * 2;
    const float* w = g_w1p + (l * HH + n) * DE;
    float w0 = w[k0], w1 = w[k0 + 1], w8 = w[k0 + 8], w9 = w[k0 + 9];
    float h0 = hif(w0), h1 = hif(w1), h8 = hif(w8), h9 = hif(w9);
    uint4 f;
    f.x = pk2(h0, h1);
    f.y = pk2(h8, h9);
    f.z = pk2(w0 - h0, w1 - h1);
    f.w = pk2(w8 - h8, w9 - h9);
    g_Bfrag[(l * 16 + nt) * 32 + lane] = f;
}

// ---------------- pre-pack W fragments (node GEMMs, K=128) ----------------
// grid = 12*128 blocks of 32; block -> (mat, ks, nt)
__global__ void k_prepW(const float* __restrict__ Wm, const float* __restrict__ Wr) {
    int m = blockIdx.x >> 7;       // 0..11
    int rem = blockIdx.x & 127;
    int ks = rem >> 4;             // 0..7
    int nt = rem & 15;             // 0..15
    const float* W = (m & 1) ? (Wr + (m >> 1) * HH * HH) : (Wm + (m >> 1) * HH * HH);
    int lane = threadIdx.x;
    int n = nt * 8 + (lane >> 2);
    int k0 = ks * 16 + (lane & 3) * 2;
    float w0 = W[n * HH + k0], w1 = W[n * HH + k0 + 1];
    float w8 = W[n * HH + k0 + 8], w9 = W[n * HH + k0 + 9];
    float h0 = hif(w0), h1 = hif(w1), h8 = hif(w8), h9 = hif(w9);
    uint4 f;
    f.x = pk2(h0, h1);
    f.y = pk2(h8, h9);
    f.z = pk2(w0 - h0, w1 - h1);
    f.w = pk2(w8 - h8, w9 - h9);
    g_Wfrag[m * 4096 + (ks * 16 + nt) * 32 + lane] = f;
}

// ---------------- CSR build ----------------
__global__ void k_hist(const int* __restrict__ ei) {
    int e = blockIdx.x * blockDim.x + threadIdx.x;
    if (e < EE) atomicAdd(&g_counts[ei[EE + e]], 1);
}

__global__ void k_scanA() {
    __shared__ int sh[1024];
    int i = blockIdx.x * 1024 + threadIdx.x;
    int v = (i < NN) ? g_counts[i] : 0;
    sh[threadIdx.x] = v;
    __syncthreads();
    for (int off = 512; off > 0; off >>= 1) {
        if (threadIdx.x < off) sh[threadIdx.x] += sh[threadIdx.x + off];
        __syncthreads();
    }
    if (threadIdx.x == 0) g_bsum[blockIdx.x] = sh[0];
}
__global__ void k_scanB() {
    if (threadIdx.x == 0) {
        int r = 0;
        for (int b = 0; b < 49; b++) { g_boff[b] = r; r += g_bsum[b]; }
    }
}
__global__ void k_scanC() {
    __shared__ int sh[1024];
    int t = threadIdx.x;
    int i = blockIdx.x * 1024 + t;
    int v = (i < NN) ? g_counts[i] : 0;
    sh[t] = v;
    __syncthreads();
    for (int off = 1; off < 1024; off <<= 1) {
        int x = (t >= off) ? sh[t - off] : 0;
        __syncthreads();
        sh[t] += x;
        __syncthreads();
    }
    if (i < NN) {
        int excl = sh[t] - v + g_boff[blockIdx.x];
        g_rowptr[i] = excl;
        g_cursor[i] = excl;
        if (i == NN - 1) g_rowptr[NN] = excl + v;
    }
}

__global__ void k_scatter(const int* __restrict__ ei, const float* __restrict__ ew) {
    int e = blockIdx.x * blockDim.x + threadIdx.x;
    if (e >= EE) return;
    int d = ei[EE + e];
    int pos = atomicAdd(&g_cursor[d], 1);
    g_perm[pos] = e;
    g_srcp[pos] = ei[e];
    float w = ew[e];
    g_ewp[pos] = fminf(fmaxf(w, 0.f), 1.f);
}

// ---------------- per-edge bias for all 6 layers via mma.sync bf16 ----------------
#define SBT_SMEM (49152 + 3072 + 3072)
__global__ __launch_bounds__(256) void k_sbias_tc(const float* __restrict__ ea) {
    extern __shared__ char smem[];
    uint4* sF = reinterpret_cast<uint4*>(smem);
    float* sB = reinterpret_cast<float*>(smem + 49152);
    float* sS = reinterpret_cast<float*>(smem + 49152 + 3072);
    for (int i = threadIdx.x; i < 3072; i += 256) sF[i] = g_Bfrag[i];
    for (int i = threadIdx.x; i < 768; i += 256) {
        sB[i] = g_b1p[i];
        sS[i] = g_sgnF[i];
    }
    __syncthreads();

    const int wid = threadIdx.x >> 5;
    const int lane = threadIdx.x & 31;
    const int rA = lane >> 2;
    const int qq = lane & 3;

    for (int tile = blockIdx.x; tile < EE / 128; tile += gridDim.x) {
        const int p0 = tile * 128 + wid * 16;
        unsigned ah[4], al[4];
        {
            int e0 = g_perm[p0 + rA];
            int e1 = g_perm[p0 + rA + 8];
            const float2* r0 = reinterpret_cast<const float2*>(ea + (size_t)e0 * DE);
            const float2* r1 = reinterpret_cast<const float2*>(ea + (size_t)e1 * DE);
            float2 x0 = r0[qq], x2 = r0[qq + 4];
            float2 y0 = r1[qq], y2 = r1[qq + 4];
            x0.x = tanh_fast(x0.x); x0.y = tanh_fast(x0.y);
            x2.x = tanh_fast(x2.x); x2.y = tanh_fast(x2.y);
            y0.x = tanh_fast(y0.x); y0.y = tanh_fast(y0.y);
            y2.x = tanh_fast(y2.x); y2.y = tanh_fast(y2.y);
            float hx0 = hif(x0.x), hx1 = hif(x0.y);
            float hx8 = hif(x2.x), hx9 = hif(x2.y);
            float hy0 = hif(y0.x), hy1 = hif(y0.y);
            float hy8 = hif(y2.x), hy9 = hif(y2.y);
            ah[0] = pk2(hx0, hx1);
            ah[1] = pk2(hy0, hy1);
            ah[2] = pk2(hx8, hx9);
            ah[3] = pk2(hy8, hy9);
            al[0] = pk2(x0.x - hx0, x0.y - hx1);
            al[1] = pk2(y0.x - hy0, y0.y - hy1);
            al[2] = pk2(x2.x - hx8, x2.y - hx9);
            al[3] = pk2(y2.x - hy8, y2.y - hy9);
        }
#pragma unroll 1
        for (int l = 0; l < LL; l++) {
            const float* bl = sB + l * HH;
            const float* sl = sS + l * HH;
            float accA = 0.f, accB = 0.f;
#pragma unroll
            for (int nt = 0; nt < 16; nt++) {
                uint4 bf = sF[(l * 16 + nt) * 32 + lane];
                float2 bb = *reinterpret_cast<const float2*>(bl + nt * 8 + qq * 2);
                float d0 = bb.x, d1 = bb.y, d2 = bb.x, d3 = bb.y;
                mma16816(d0, d1, d2, d3, ah[0], ah[1], ah[2], ah[3], bf.x, bf.y,
                         d0, d1, d2, d3);
                mma16816(d0, d1, d2, d3, al[0], al[1], al[2], al[3], bf.x, bf.y,
                         d0, d1, d2, d3);
                mma16816(d0, d1, d2, d3, ah[0], ah[1], ah[2], ah[3], bf.z, bf.w,
                         d0, d1, d2, d3);
                float2 ss = *reinterpret_cast<const float2*>(sl + nt * 8 + qq * 2);
                accA = fmaf(fmaxf(d0 * ss.x, 0.f), ss.x, accA);
                accA = fmaf(fmaxf(d1 * ss.y, 0.f), ss.y, accA);
                accB = fmaf(fmaxf(d2 * ss.x, 0.f), ss.x, accB);
                accB = fmaf(fmaxf(d3 * ss.y, 0.f), ss.y, accB);
            }
            accA += __shfl_xor_sync(0xffffffffu, accA, 1);
            accA += __shfl_xor_sync(0xffffffffu, accA, 2);
            accB += __shfl_xor_sync(0xffffffffu, accB, 1);
            accB += __shfl_xor_sync(0xffffffffu, accB, 2);
            if (qq == 0) {
                float c = g_be2s[l];
                g_sb[(size_t)l * EE + p0 + rA] = accA + c;
                g_sb[(size_t)l * EE + p0 + rA + 8] = accB + c;
            }
        }
    }
}

// ---------------- tensor-core node GEMM: C = act(A @ W^T + b) ----------------
// a_sel: 1=g_ha, 2=g_a2 ; c_sel: 0=g_ha, 1=g_msg ; do_scores fuses s_src/s_dst
#define GT_SMEM (65536 + 512 + 1024)
__global__ __launch_bounds__(256) void k_gemm_tc(int a_sel, int mat,
                                                 const float* __restrict__ bias,
                                                 int c_sel, int do_relu,
                                                 int do_scores, int l) {
    extern __shared__ char smem[];
    uint4* sW = reinterpret_cast<uint4*>(smem);                    // 4096 uint4
    float* sBias = reinterpret_cast<float*>(smem + 65536);         // 128
    float* sCas = reinterpret_cast<float*>(smem + 65536 + 512);    // 128
    float* sCad = sCas + 128;                                      // 128

    const float* A = (a_sel == 1) ? g_ha : g_a2;
    float* C = (c_sel == 0) ? g_ha : g_msg;
    const uint4* Wf = g_Wfrag + (size_t)mat * 4096;

    for (int i = threadIdx.x; i < 4096; i += 256) sW[i] = Wf[i];
    if (threadIdx.x < 128) {
        sBias[threadIdx.x] = bias[threadIdx.x];
        if (do_scores) {
            sCas[threadIdx.x] = g_cas[l * HH + threadIdx.x];
            sCad[threadIdx.x] = g_cad[l * HH + threadIdx.x];
        }
    }
    __syncthreads();

    const int wid = threadIdx.x >> 5;
    const int lane = threadIdx.x & 31;
    const int rA = lane >> 2;
    const int qq = lane & 3;

    const int row0 = blockIdx.x * 128 + wid * 16 + rA;   // second row: row0+8
    const int r0 = (row0 < NN) ? row0 : (NN - 1);
    const int r1 = (row0 + 8 < NN) ? (row0 + 8) : (NN - 1);

    float acc[16][4];
#pragma unroll
    for (int nt = 0; nt < 16; nt++)
#pragma unroll
        for (int j = 0; j < 4; j++) acc[nt][j] = 0.f;

    float vs0 = 0.f, vd0 = 0.f, vs1 = 0.f, vd1 = 0.f;

#pragma unroll 1
    for (int ks = 0; ks < 8; ks++) {
        const float* ar0 = A + (size_t)r0 * HH + ks * 16;
        const float* ar1 = A + (size_t)r1 * HH + ks * 16;
        float2 x0 = *reinterpret_cast<const float2*>(ar0 + qq * 2);
        float2 x8 = *reinterpret_cast<const float2*>(ar0 + qq * 2 + 8);
        float2 y0 = *reinterpret_cast<const float2*>(ar1 + qq * 2);
        float2 y8 = *reinterpret_cast<const float2*>(ar1 + qq * 2 + 8);
        if (do_scores) {
            int c0 = ks * 16 + qq * 2;
            vs0 += x0.x * sCas[c0] + x0.y * sCas[c0 + 1]
                 + x8.x * sCas[c0 + 8] + x8.y * sCas[c0 + 9];
            vd0 += x0.x * sCad[c0] + x0.y * sCad[c0 + 1]
                 + x8.x * sCad[c0 + 8] + x8.y * sCad[c0 + 9];
            vs1 += y0.x * sCas[c0] + y0.y * sCas[c0 + 1]
                 + y8.x * sCas[c0 + 8] + y8.y * sCas[c0 + 9];
            vd1 += y0.x * sCad[c0] + y0.y * sCad[c0 + 1]
                 + y8.x * sCad[c0 + 8] + y8.y * sCad[c0 + 9];
        }
        float hx0 = hif(x0.x), hx1 = hif(x0.y), hx8 = hif(x8.x), hx9 = hif(x8.y);
        float hy0 = hif(y0.x), hy1 = hif(y0.y), hy8 = hif(y8.x), hy9 = hif(y8.y);
        unsigned ah0 = pk2(hx0, hx1), ah1 = pk2(hy0, hy1);
        unsigned ah2 = pk2(hx8, hx9), ah3 = pk2(hy8, hy9);
        unsigned al0 = pk2(x0.x - hx0, x0.y - hx1);
        unsigned al1 = pk2(y0.x - hy0, y0.y - hy1);
        unsigned al2 = pk2(x8.x - hx8, x8.y - hx9);
        unsigned al3 = pk2(y8.x - hy8, y8.y - hy9);
        const uint4* wrow = sW + ks * 512 + lane;
#pragma unroll
        for (int nt = 0; nt < 16; nt++) {
            uint4 bf = wrow[nt * 32];
            mma16816(acc[nt][0], acc[nt][1], acc[nt][2], acc[nt][3],
                     ah0, ah1, ah2, ah3, bf.x, bf.y,
                     acc[nt][0], acc[nt][1], acc[nt][2], acc[nt][3]);
            mma16816(acc[nt][0], acc[nt][1], acc[nt][2], acc[nt][3],
                     al0, al1, al2, al3, bf.x, bf.y,
                     acc[nt][0], acc[nt][1], acc[nt][2], acc[nt][3]);
            mma16816(acc[nt][0], acc[nt][1], acc[nt][2], acc[nt][3],
                     ah0, ah1, ah2, ah3, bf.z, bf.w,
                     acc[nt][0], acc[nt][1], acc[nt][2], acc[nt][3]);
        }
    }

    if (do_scores) {
        vs0 += __shfl_xor_sync(0xffffffffu, vs0, 1);
        vs0 += __shfl_xor_sync(0xffffffffu, vs0, 2);
        vd0 += __shfl_xor_sync(0xffffffffu, vd0, 1);
        vd0 += __shfl_xor_sync(0xffffffffu, vd0, 2);
        vs1 += __shfl_xor_sync(0xffffffffu, vs1, 1);
        vs1 += __shfl_xor_sync(0xffffffffu, vs1, 2);
        vd1 += __shfl_xor_sync(0xffffffffu, vd1, 1);
        vd1 += __shfl_xor_sync(0xffffffffu, vd1, 2);
        if (qq == 0) {
            float ba = g_bass[l], bd = g_bads[l];
            if (row0 < NN) { g_ssrc[row0] = vs0 + ba; g_sdst[row0] = vd0 + bd; }
            if (row0 + 8 < NN) { g_ssrc[row0 + 8] = vs1 + ba; g_sdst[row0 + 8] = vd1 + bd; }
        }
    }

    const bool st0 = (row0 < NN);
    const bool st1 = (row0 + 8 < NN);
#pragma unroll
    for (int nt = 0; nt < 16; nt++) {
        float2 bb = *reinterpret_cast<const float2*>(sBias + nt * 8 + qq * 2);
        float o0 = acc[nt][0] + bb.x, o1 = acc[nt][1] + bb.y;
        float o2 = acc[nt][2] + bb.x, o3 = acc[nt][3] + bb.y;
        if (do_relu) {
            o0 = fmaxf(o0, 0.f); o1 = fmaxf(o1, 0.f);
            o2 = fmaxf(o2, 0.f); o3 = fmaxf(o3, 0.f);
        }
        if (st0)
            *reinterpret_cast<float2*>(C + (size_t)row0 * HH + nt * 8 + qq * 2) =
                make_float2(o0, o1);
        if (st1)
            *reinterpret_cast<float2*>(C + (size_t)(row0 + 8) * HH + nt * 8 + qq * 2) =
                make_float2(o2, o3);
    }
}

// ---------------- fp32 GEMM for input projection (K=64, runs once) ----------------
__global__ __launch_bounds__(256, 2) void k_gemm(const float* __restrict__ A,
                                                 const float* __restrict__ W,
                                                 const float* __restrict__ bias,
                                                 int nrows, int K) {
    float* C = g_ha;
    __shared__ __align__(16) float As[128][33];
    __shared__ __align__(16) float Ws[32][128];

    int tid = threadIdx.x;
    int bm = blockIdx.x * 128;
    int tx = tid & 15;
    int ty = tid >> 4;
    int n0 = tx * 8;
    int m0 = ty * 8;

    float acc[8][8];
#pragma unroll
    for (int i = 0; i < 8; i++)
#pragma unroll
        for (int j = 0; j < 8; j++) acc[i][j] = 0.f;

    int nch = K >> 5;
    for (int ch = 0; ch < nch; ch++) {
        int k0 = ch * 32;
#pragma unroll
        for (int i = 0; i < 4; i++) {
            int idx = tid + i * 256;
            int m = idx >> 3;
            int kq = (idx & 7) * 4;
            float4 v = make_float4(0.f, 0.f, 0.f, 0.f);
            int gr = bm + m;
            if (gr < nrows)
                v = *reinterpret_cast<const float4*>(A + (size_t)gr * K + k0 + kq);
            As[m][kq] = v.x; As[m][kq + 1] = v.y; As[m][kq + 2] = v.z; As[m][kq + 3] = v.w;
        }
#pragma unroll
        for (int i = 0; i < 4; i++) {
            int idx = tid + i * 256;
            int n = idx >> 3;
            int kq = (idx & 7) * 4;
            float4 v = *reinterpret_cast<const float4*>(W + (size_t)n * K + k0 + kq);
            Ws[kq][n] = v.x; Ws[kq + 1][n] = v.y; Ws[kq + 2][n] = v.z; Ws[kq + 3][n] = v.w;
        }
        __syncthreads();
#pragma unroll 8
        for (int kk = 0; kk < 32; kk++) {
            float a[8];
#pragma unroll
            for (int i = 0; i < 8; i++) a[i] = As[m0 + i][kk];
            float4 b0 = *reinterpret_cast<const float4*>(&Ws[kk][n0]);
            float4 b1 = *reinterpret_cast<const float4*>(&Ws[kk][n0 + 4]);
#pragma unroll
            for (int i = 0; i < 8; i++) {
                acc[i][0] = fmaf(a[i], b0.x, acc[i][0]);
                acc[i][1] = fmaf(a[i], b0.y, acc[i][1]);
                acc[i][2] = fmaf(a[i], b0.z, acc[i][2]);
                acc[i][3] = fmaf(a[i], b0.w, acc[i][3]);
                acc[i][4] = fmaf(a[i], b1.x, acc[i][4]);
                acc[i][5] = fmaf(a[i], b1.y, acc[i][5]);
                acc[i][6] = fmaf(a[i], b1.z, acc[i][6]);
                acc[i][7] = fmaf(a[i], b1.w, acc[i][7]);
            }
        }
        __syncthreads();
    }

    float4 bv0 = *reinterpret_cast<const float4*>(bias + n0);
    float4 bv1 = *reinterpret_cast<const float4*>(bias + n0 + 4);
#pragma unroll
    for (int i = 0; i < 8; i++) {
        int gr = bm + m0 + i;
        if (gr >= nrows) continue;
        float4 o0, o1;
        o0.x = fmaxf(acc[i][0] + bv0.x, 0.f); o0.y = fmaxf(acc[i][1] + bv0.y, 0.f);
        o0.z = fmaxf(acc[i][2] + bv0.z, 0.f); o0.w = fmaxf(acc[i][3] + bv0.w, 0.f);
        o1.x = fmaxf(acc[i][4] + bv1.x, 0.f); o1.y = fmaxf(acc[i][5] + bv1.y, 0.f);
        o1.z = fmaxf(acc[i][6] + bv1.z, 0.f); o1.w = fmaxf(acc[i][7] + bv1.w, 0.f);
        float* cp = C + (size_t)gr * HH + n0;
        *reinterpret_cast<float4*>(cp) = o0;
        *reinterpret_cast<float4*>(cp + 4) = o1;
    }
}

// ---------------- gather-aggregate: warp per destination node over CSR ----------------
__global__ void k_agg(int l) {
    int gw = (blockIdx.x * blockDim.x + threadIdx.x) >> 5;
    int lane = threadIdx.x & 31;
    if (gw >= NN) return;
    int n = gw;
    int beg = g_rowptr[n];
    int end = g_rowptr[n + 1];
    float sdn = g_sdst[n];
    const float* __restrict__ sb = g_sb + (size_t)l * EE;
    const float4* __restrict__ msg4 = reinterpret_cast<const float4*>(g_msg);
    float4 acc = make_float4(0.f, 0.f, 0.f, 0.f);
    int p = beg;
    for (; p + 1 < end; p += 2) {
        int s0 = g_srcp[p];
        int s1 = g_srcp[p + 1];
        float x0 = g_ssrc[s0] + sdn + sb[p];
        float x1 = g_ssrc[s1] + sdn + sb[p + 1];
        float gt0 = g_ewp[p] / (1.f + __expf(-x0));
        float gt1 = g_ewp[p + 1] / (1.f + __expf(-x1));
        float4 m0 = msg4[s0 * 32 + lane];
        float4 m1 = msg4[s1 * 32 + lane];
        acc.x = fmaf(m0.x, gt0, acc.x); acc.y = fmaf(m0.y, gt0, acc.y);
        acc.z = fmaf(m0.z, gt0, acc.z); acc.w = fmaf(m0.w, gt0, acc.w);
        acc.x = fmaf(m1.x, gt1, acc.x); acc.y = fmaf(m1.y, gt1, acc.y);
        acc.z = fmaf(m1.z, gt1, acc.z); acc.w = fmaf(m1.w, gt1, acc.w);
    }
    if (p < end) {
        int s0 = g_srcp[p];
        float x0 = g_ssrc[s0] + sdn + sb[p];
        float gt0 = g_ewp[p] / (1.f + __expf(-x0));
        float4 m0 = msg4[s0 * 32 + lane];
        acc.x = fmaf(m0.x, gt0, acc.x); acc.y = fmaf(m0.y, gt0, acc.y);
        acc.z = fmaf(m0.z, gt0, acc.z); acc.w = fmaf(m0.w, gt0, acc.w);
    }
    float4 h4 = reinterpret_cast<const float4*>(g_ha)[(size_t)n * 32 + lane];
    float4 o;
    o.x = h4.x + acc.x; o.y = h4.y + acc.y; o.z = h4.z + acc.z; o.w = h4.w + acc.w;
    reinterpret_cast<float4*>(g_a2)[(size_t)n * 32 + lane] = o;
}

// ---------------- graph readout ----------------
__global__ void k_grep() {
    int c = threadIdx.x & 127;
    int half = threadIdx.x >> 7;
    int rs = blockIdx.x * 196;
    int re = rs + 196;
    if (re > NN) re = NN;
    float acc = 0.f;
    for (int r = rs + half; r < re; r += 2) acc += g_ha[(size_t)r * HH + c];
    __shared__ float sr[256];
    sr[threadIdx.x] = acc;
    __syncthreads();
    if (threadIdx.x < 128)
        g_gpart[blockIdx.x * HH + threadIdx.x] = sr[threadIdx.x] + sr[threadIdx.x + 128];
}

__global__ void k_final(const float* __restrict__ W_out, const float* __restrict__ b_out,
                        float* __restrict__ out) {
    int t = threadIdx.x;  // 128 threads
    float s = 0.f;
    for (int b = 0; b < 256; b++) s += g_gpart[b * HH + t];
    float v = s * (1.f / (float)NN) * W_out[t];
    __shared__ float r[128];
    r[t] = v;
    __syncthreads();
    for (int off = 64; off; off >>= 1) {
        if (t < off) r[t] += r[t + off];
        __syncthreads();
    }
    if (t == 0) out[0] = (r[0] + b_out[0]) * (1.f / 50.f);
}

// ---------------- launch ----------------
extern "C" void kernel_launch(void* const* d_in, const int* in_sizes, int n_in,
                              void* d_out, int out_size) {
    const float* x      = (const float*)d_in[0];
    const int*   ei     = (const int*)d_in[1];
    const float* ew     = (const float*)d_in[2];
    const float* ea     = (const float*)d_in[3];
    const float* W_in   = (const float*)d_in[4];
    const float* b_in   = (const float*)d_in[5];
    const float* W_e1   = (const float*)d_in[6];
    const float* b_e1   = (const float*)d_in[7];
    const float* W_e2   = (const float*)d_in[8];
    const float* b_e2   = (const float*)d_in[9];
    const float* W_as   = (const float*)d_in[10];
    const float* b_as   = (const float*)d_in[11];
    const float* W_ad   = (const float*)d_in[12];
    const float* b_ad   = (const float*)d_in[13];
    const float* W_m    = (const float*)d_in[14];
    const float* b_m    = (const float*)d_in[15];
    const float* W_r    = (const float*)d_in[16];
    const float* b_r    = (const float*)d_in[17];
    const float* W_out  = (const float*)d_in[18];
    const float* b_out  = (const float*)d_in[19];
    float* out = (float*)d_out;

    cudaFuncSetAttribute(k_sbias_tc, cudaFuncAttributeMaxDynamicSharedMemorySize, SBT_SMEM);
    cudaFuncSetAttribute(k_gemm_tc, cudaFuncAttributeMaxDynamicSharedMemorySize, GT_SMEM);

    const int gridE = (EE + 255) / 256;   // 6250
    const int gridN = (NN + 255) / 256;   // 196
    const int gridG = (NN + 127) / 128;   // 391

    k_init<<<gridN, 256>>>();
    k_prep<<<LL, HH>>>(W_e1, b_e1, W_e2, b_e2, W_as, b_as, W_ad, b_ad);
    k_prepB<<<LL * 16, 32>>>();
    k_prepW<<<12 * 128, 32>>>(W_m, W_r);
    k_hist<<<gridE, 256>>>(ei);
    k_scanA<<<49, 1024>>>();
    k_scanB<<<1, 32>>>();
    k_scanC<<<49, 1024>>>();
    k_scatter<<<gridE, 256>>>(ei, ew);
    // input projection: ha = relu(x @ W_in^T + b_in)
    k_gemm<<<gridG, 256>>>(x, W_in, b_in, NN, DIN);
    // per-edge bias for all 6 layers (CSR order), tensor cores via mma.sync
    k_sbias_tc<<<625, 256, SBT_SMEM>>>(ea);

    for (int l = 0; l < LL; l++) {
        // msg = ha @ W_m^T + b_m  (+ fused s_src/s_dst scores)
        k_gemm_tc<<<gridG, 256, GT_SMEM>>>(1, l * 2 + 0, b_m + l * HH, 1, 0, 1, l);
        // a2 = ha + segment_sum(msg[src] * gate)
        k_agg<<<gridE, 256>>>(l);
        // ha = relu(a2 @ W_r^T + b_r)
        k_gemm_tc<<<gridG, 256, GT_SMEM>>>(2, l * 2 + 1, b_r + l * HH, 0, 1, 0, l);
    }

    k_grep<<<256, 256>>>();
    k_final<<<1, 128>>>(W_out, b_out, out);
}

// round 14
// speedup vs baseline: 1.7376x; 1.0040x over previous
#include <cuda_runtime.h>
#include <cuda_bf16.h>
#include <cuda_fp16.h>
#include <math.h>
#include <stdint.h>

#define NN 50000
#define EE 1600000
#define HH 128
#define DIN 64
#define DE 16
#define LL 6

// ---------------- scratch (static __device__ globals; no allocation) ----------------
__device__ float g_ha[NN * HH];     // node features (always post-relu)
__device__ __half g_msgh[NN * HH];  // per-node message linear output (fp16)
__device__ float g_a2[NN * HH];     // ha + agg (input to update GEMM)
__device__ float g_ssrc[NN];
__device__ float g_sdst[NN];
__device__ float g_sb[(size_t)LL * EE];  // per-layer per-edge bias (CSR order)
__device__ int g_counts[NN];
__device__ int g_rowptr[NN + 1];
__device__ int g_cursor[NN];
__device__ int g_perm[EE];   // csr pos -> original edge id
__device__ int g_srcp[EE];   // csr-ordered src index
__device__ float g_ewp[EE];  // csr-ordered clipped edge weight
__device__ float g_w1p[LL * HH * DE];  // W_e1 * colsum(W_e2)  (SIGNED fold)
__device__ float g_b1p[LL * HH];       // b_e1 * colsum(W_e2)
__device__ float g_sgnF[LL * HH];      // sign(colsum(W_e2)) as +-1.0f
__device__ float g_cas[LL * HH];       // colsum(W_as)
__device__ float g_cad[LL * HH];       // colsum(W_ad)
__device__ float g_be2s[LL];
__device__ float g_bass[LL];
__device__ float g_bads[LL];
__device__ float g_gpart[256 * HH];
__device__ int g_bsum[49];
__device__ int g_boff[49];
// pre-packed B fragments for edge-MLP mma: [l][ntile][lane] -> {b0_hi, b1_hi, b0_lo, b1_lo}
__device__ __align__(16) uint4 g_Bfrag[LL * 16 * 32];
// pre-packed W fragments for node GEMMs: 12 matrices (l*2: W_m, l*2+1: W_r), each
// [ks 0..7][nt 0..15][lane 0..31] -> {b0_hi, b1_hi, b0_lo, b1_lo}
__device__ __align__(16) uint4 g_Wfrag[12 * 4096];

// ---------------- small helpers ----------------
__device__ __forceinline__ float tanh_fast(float x) {
    float y;
    asm("tanh.approx.f32 %0, %1;" : "=f"(y) : "f"(x));
    return y;
}
__device__ __forceinline__ unsigned pk2(float a, float b) {
    __nv_bfloat162 t = __floats2bfloat162_rn(a, b);
    return *reinterpret_cast<unsigned*>(&t);
}
__device__ __forceinline__ float hif(float a) {
    return __bfloat162float(__float2bfloat16(a));
}
__device__ __forceinline__ void mma16816(float& d0, float& d1, float& d2, float& d3,
                                         unsigned a0, unsigned a1, unsigned a2, unsigned a3,
                                         unsigned b0, unsigned b1,
                                         float c0, float c1, float c2, float c3) {
    asm volatile(
        "mma.sync.aligned.m16n8k16.row.col.f32.bf16.bf16.f32 "
        "{%0,%1,%2,%3}, {%4,%5,%6,%7}, {%8,%9}, {%10,%11,%12,%13};"
        : "=f"(d0), "=f"(d1), "=f"(d2), "=f"(d3)
        : "r"(a0), "r"(a1), "r"(a2), "r"(a3), "r"(b0), "r"(b1),
          "f"(c0), "f"(c1), "f"(c2), "f"(c3));
}

// ---------------- init: zero histogram counters ----------------
__global__ void k_init() {
    int i = blockIdx.x * blockDim.x + threadIdx.x;
    if (i < NN) g_counts[i] = 0;
}

// ---------------- precompute column sums / folded edge-MLP weights ----------------
__global__ void k_prep(const float* __restrict__ W_e1, const float* __restrict__ b_e1,
                       const float* __restrict__ W_e2, const float* __restrict__ b_e2,
                       const float* __restrict__ W_as, const float* __restrict__ b_as,
                       const float* __restrict__ W_ad, const float* __restrict__ b_ad) {
    int l = blockIdx.x;       // 0..5
    int t = threadIdx.x;      // 0..127
    const float* was = W_as + l * HH * HH;
    const float* wad = W_ad + l * HH * HH;
    const float* we2 = W_e2 + l * HH * HH;
    float sa = 0.f, sd = 0.f, s2 = 0.f;
    for (int j = 0; j < HH; j++) {
        sa += was[j * HH + t];
        sd += wad[j * HH + t];
        s2 += we2[j * HH + t];
    }
    g_cas[l * HH + t] = sa;
    g_cad[l * HH + t] = sd;
    // SIGNED fold: x_unit = colsum * (W_e1 . t + b_e1); contribution = s*max(s*x,0)
    g_b1p[l * HH + t] = b_e1[l * HH + t] * s2;
    g_sgnF[l * HH + t] = (s2 < 0.f) ? -1.f : 1.f;
    const float* we1 = W_e1 + (l * HH + t) * DE;
    float* w1p = g_w1p + (l * HH + t) * DE;
    for (int k = 0; k < DE; k++) w1p[k] = we1[k] * s2;
    if (t == 0) {
        float s = 0.f;
        for (int j = 0; j < HH; j++) s += b_e2[l * HH + j];
        g_be2s[l] = s;
        s = 0.f;
        for (int j = 0; j < HH; j++) s += b_as[l * HH + j];
        g_bass[l] = s;
        s = 0.f;
        for (int j = 0; j < HH; j++) s += b_ad[l * HH + j];
        g_bads[l] = s;
    }
}

// ---------------- pre-pack B fragments (edge MLP, K=16) ----------------
__global__ void k_prepB() {
    int l = blockIdx.x >> 4;       // 0..5
    int nt = blockIdx.x & 15;      // 0..15
    int lane = threadIdx.x;        // 0..31
    int n = nt * 8 + (lane >> 2);
    int k0 = (lane & 3) * 2;
    const float* w = g_w1p + (l * HH + n) * DE;
    float w0 = w[k0], w1 = w[k0 + 1], w8 = w[k0 + 8], w9 = w[k0 + 9];
    float h0 = hif(w0), h1 = hif(w1), h8 = hif(w8), h9 = hif(w9);
    uint4 f;
    f.x = pk2(h0, h1);
    f.y = pk2(h8, h9);
    f.z = pk2(w0 - h0, w1 - h1);
    f.w = pk2(w8 - h8, w9 - h9);
    g_Bfrag[(l * 16 + nt) * 32 + lane] = f;
}

// ---------------- pre-pack W fragments (node GEMMs, K=128) ----------------
__global__ void k_prepW(const float* __restrict__ Wm, const float* __restrict__ Wr) {
    int m = blockIdx.x >> 7;       // 0..11
    int rem = blockIdx.x & 127;
    int ks = rem >> 4;             // 0..7
    int nt = rem & 15;             // 0..15
    const float* W = (m & 1) ? (Wr + (m >> 1) * HH * HH) : (Wm + (m >> 1) * HH * HH);
    int lane = threadIdx.x;
    int n = nt * 8 + (lane >> 2);
    int k0 = ks * 16 + (lane & 3) * 2;
    float w0 = W[n * HH + k0], w1 = W[n * HH + k0 + 1];
    float w8 = W[n * HH + k0 + 8], w9 = W[n * HH + k0 + 9];
    float h0 = hif(w0), h1 = hif(w1), h8 = hif(w8), h9 = hif(w9);
    uint4 f;
    f.x = pk2(h0, h1);
    f.y = pk2(h8, h9);
    f.z = pk2(w0 - h0, w1 - h1);
    f.w = pk2(w8 - h8, w9 - h9);
    g_Wfrag[m * 4096 + (ks * 16 + nt) * 32 + lane] = f;
}

// ---------------- CSR build ----------------
__global__ void k_hist(const int* __restrict__ ei) {
    int e = blockIdx.x * blockDim.x + threadIdx.x;
    if (e < EE) atomicAdd(&g_counts[ei[EE + e]], 1);
}

__global__ void k_scanA() {
    __shared__ int sh[1024];
    int i = blockIdx.x * 1024 + threadIdx.x;
    int v = (i < NN) ? g_counts[i] : 0;
    sh[threadIdx.x] = v;
    __syncthreads();
    for (int off = 512; off > 0; off >>= 1) {
        if (threadIdx.x < off) sh[threadIdx.x] += sh[threadIdx.x + off];
        __syncthreads();
    }
    if (threadIdx.x == 0) g_bsum[blockIdx.x] = sh[0];
}
__global__ void k_scanB() {
    if (threadIdx.x == 0) {
        int r = 0;
        for (int b = 0; b < 49; b++) { g_boff[b] = r; r += g_bsum[b]; }
    }
}
__global__ void k_scanC() {
    __shared__ int sh[1024];
    int t = threadIdx.x;
    int i = blockIdx.x * 1024 + t;
    int v = (i < NN) ? g_counts[i] : 0;
    sh[t] = v;
    __syncthreads();
    for (int off = 1; off < 1024; off <<= 1) {
        int x = (t >= off) ? sh[t - off] : 0;
        __syncthreads();
        sh[t] += x;
        __syncthreads();
    }
    if (i < NN) {
        int excl = sh[t] - v + g_boff[blockIdx.x];
        g_rowptr[i] = excl;
        g_cursor[i] = excl;
        if (i == NN - 1) g_rowptr[NN] = excl + v;
    }
}

__global__ void k_scatter(const int* __restrict__ ei, const float* __restrict__ ew) {
    int e = blockIdx.x * blockDim.x + threadIdx.x;
    if (e >= EE) return;
    int d = ei[EE + e];
    int pos = atomicAdd(&g_cursor[d], 1);
    g_perm[pos] = e;
    g_srcp[pos] = ei[e];
    float w = ew[e];
    g_ewp[pos] = fminf(fmaxf(w, 0.f), 1.f);
}

// ---------------- per-edge bias for all 6 layers via mma.sync bf16 ----------------
#define SBT_SMEM (49152 + 3072 + 3072)
__global__ __launch_bounds__(256) void k_sbias_tc(const float* __restrict__ ea) {
    extern __shared__ char smem[];
    uint4* sF = reinterpret_cast<uint4*>(smem);
    float* sB = reinterpret_cast<float*>(smem + 49152);
    float* sS = reinterpret_cast<float*>(smem + 49152 + 3072);
    for (int i = threadIdx.x; i < 3072; i += 256) sF[i] = g_Bfrag[i];
    for (int i = threadIdx.x; i < 768; i += 256) {
        sB[i] = g_b1p[i];
        sS[i] = g_sgnF[i];
    }
    __syncthreads();

    const int wid = threadIdx.x >> 5;
    const int lane = threadIdx.x & 31;
    const int rA = lane >> 2;
    const int qq = lane & 3;

    for (int tile = blockIdx.x; tile < EE / 128; tile += gridDim.x) {
        const int p0 = tile * 128 + wid * 16;
        unsigned ah[4], al[4];
        {
            int e0 = g_perm[p0 + rA];
            int e1 = g_perm[p0 + rA + 8];
            const float2* r0 = reinterpret_cast<const float2*>(ea + (size_t)e0 * DE);
            const float2* r1 = reinterpret_cast<const float2*>(ea + (size_t)e1 * DE);
            float2 x0 = r0[qq], x2 = r0[qq + 4];
            float2 y0 = r1[qq], y2 = r1[qq + 4];
            x0.x = tanh_fast(x0.x); x0.y = tanh_fast(x0.y);
            x2.x = tanh_fast(x2.x); x2.y = tanh_fast(x2.y);
            y0.x = tanh_fast(y0.x); y0.y = tanh_fast(y0.y);
            y2.x = tanh_fast(y2.x); y2.y = tanh_fast(y2.y);
            float hx0 = hif(x0.x), hx1 = hif(x0.y);
            float hx8 = hif(x2.x), hx9 = hif(x2.y);
            float hy0 = hif(y0.x), hy1 = hif(y0.y);
            float hy8 = hif(y2.x), hy9 = hif(y2.y);
            ah[0] = pk2(hx0, hx1);
            ah[1] = pk2(hy0, hy1);
            ah[2] = pk2(hx8, hx9);
            ah[3] = pk2(hy8, hy9);
            al[0] = pk2(x0.x - hx0, x0.y - hx1);
            al[1] = pk2(y0.x - hy0, y0.y - hy1);
            al[2] = pk2(x2.x - hx8, x2.y - hx9);
            al[3] = pk2(y2.x - hy8, y2.y - hy9);
        }
#pragma unroll 1
        for (int l = 0; l < LL; l++) {
            const float* bl = sB + l * HH;
            const float* sl = sS + l * HH;
            float accA = 0.f, accB = 0.f;
#pragma unroll
            for (int nt = 0; nt < 16; nt++) {
                uint4 bf = sF[(l * 16 + nt) * 32 + lane];
                float2 bb = *reinterpret_cast<const float2*>(bl + nt * 8 + qq * 2);
                float d0 = bb.x, d1 = bb.y, d2 = bb.x, d3 = bb.y;
                mma16816(d0, d1, d2, d3, ah[0], ah[1], ah[2], ah[3], bf.x, bf.y,
                         d0, d1, d2, d3);
                mma16816(d0, d1, d2, d3, al[0], al[1], al[2], al[3], bf.x, bf.y,
                         d0, d1, d2, d3);
                mma16816(d0, d1, d2, d3, ah[0], ah[1], ah[2], ah[3], bf.z, bf.w,
                         d0, d1, d2, d3);
                float2 ss = *reinterpret_cast<const float2*>(sl + nt * 8 + qq * 2);
                accA = fmaf(fmaxf(d0 * ss.x, 0.f), ss.x, accA);
                accA = fmaf(fmaxf(d1 * ss.y, 0.f), ss.y, accA);
                accB = fmaf(fmaxf(d2 * ss.x, 0.f), ss.x, accB);
                accB = fmaf(fmaxf(d3 * ss.y, 0.f), ss.y, accB);
            }
            accA += __shfl_xor_sync(0xffffffffu, accA, 1);
            accA += __shfl_xor_sync(0xffffffffu, accA, 2);
            accB += __shfl_xor_sync(0xffffffffu, accB, 1);
            accB += __shfl_xor_sync(0xffffffffu, accB, 2);
            if (qq == 0) {
                float c = g_be2s[l];
                g_sb[(size_t)l * EE + p0 + rA] = accA + c;
                g_sb[(size_t)l * EE + p0 + rA + 8] = accB + c;
            }
        }
    }
}

// ---------------- tensor-core node GEMM: C = act(A @ W^T + b) ----------------
// a_sel: 1=g_ha, 2=g_a2 ; c_sel: 0=g_ha(f32), 1=g_msgh(f16) ; do_scores fuses s_src/s_dst
#define GT_SMEM (65536 + 512 + 1024)
__global__ __launch_bounds__(256) void k_gemm_tc(int a_sel, int mat,
                                                 const float* __restrict__ bias,
                                                 int c_sel, int do_relu,
                                                 int do_scores, int l) {
    extern __shared__ char smem[];
    uint4* sW = reinterpret_cast<uint4*>(smem);                    // 4096 uint4
    float* sBias = reinterpret_cast<float*>(smem + 65536);         // 128
    float* sCas = reinterpret_cast<float*>(smem + 65536 + 512);    // 128
    float* sCad = sCas + 128;                                      // 128

    const float* A = (a_sel == 1) ? g_ha : g_a2;
    const uint4* Wf = g_Wfrag + (size_t)mat * 4096;

    for (int i = threadIdx.x; i < 4096; i += 256) sW[i] = Wf[i];
    if (threadIdx.x < 128) {
        sBias[threadIdx.x] = bias[threadIdx.x];
        if (do_scores) {
            sCas[threadIdx.x] = g_cas[l * HH + threadIdx.x];
            sCad[threadIdx.x] = g_cad[l * HH + threadIdx.x];
        }
    }
    __syncthreads();

    const int wid = threadIdx.x >> 5;
    const int lane = threadIdx.x & 31;
    const int rA = lane >> 2;
    const int qq = lane & 3;

    const int row0 = blockIdx.x * 128 + wid * 16 + rA;   // second row: row0+8
    const int r0 = (row0 < NN) ? row0 : (NN - 1);
    const int r1 = (row0 + 8 < NN) ? (row0 + 8) : (NN - 1);

    float acc[16][4];
#pragma unroll
    for (int nt = 0; nt < 16; nt++)
#pragma unroll
        for (int j = 0; j < 4; j++) acc[nt][j] = 0.f;

    float vs0 = 0.f, vd0 = 0.f, vs1 = 0.f, vd1 = 0.f;

#pragma unroll 1
    for (int ks = 0; ks < 8; ks++) {
        const float* ar0 = A + (size_t)r0 * HH + ks * 16;
        const float* ar1 = A + (size_t)r1 * HH + ks * 16;
        float2 x0 = *reinterpret_cast<const float2*>(ar0 + qq * 2);
        float2 x8 = *reinterpret_cast<const float2*>(ar0 + qq * 2 + 8);
        float2 y0 = *reinterpret_cast<const float2*>(ar1 + qq * 2);
        float2 y8 = *reinterpret_cast<const float2*>(ar1 + qq * 2 + 8);
        if (do_scores) {
            int c0 = ks * 16 + qq * 2;
            vs0 += x0.x * sCas[c0] + x0.y * sCas[c0 + 1]
                 + x8.x * sCas[c0 + 8] + x8.y * sCas[c0 + 9];
            vd0 += x0.x * sCad[c0] + x0.y * sCad[c0 + 1]
                 + x8.x * sCad[c0 + 8] + x8.y * sCad[c0 + 9];
            vs1 += y0.x * sCas[c0] + y0.y * sCas[c0 + 1]
                 + y8.x * sCas[c0 + 8] + y8.y * sCas[c0 + 9];
            vd1 += y0.x * sCad[c0] + y0.y * sCad[c0 + 1]
                 + y8.x * sCad[c0 + 8] + y8.y * sCad[c0 + 9];
        }
        float hx0 = hif(x0.x), hx1 = hif(x0.y), hx8 = hif(x8.x), hx9 = hif(x8.y);
        float hy0 = hif(y0.x), hy1 = hif(y0.y), hy8 = hif(y8.x), hy9 = hif(y8.y);
        unsigned ah0 = pk2(hx0, hx1), ah1 = pk2(hy0, hy1);
        unsigned ah2 = pk2(hx8, hx9), ah3 = pk2(hy8, hy9);
        unsigned al0 = pk2(x0.x - hx0, x0.y - hx1);
        unsigned al1 = pk2(y0.x - hy0, y0.y - hy1);
        unsigned al2 = pk2(x8.x - hx8, x8.y - hx9);
        unsigned al3 = pk2(y8.x - hy8, y8.y - hy9);
        const uint4* wrow = sW + ks * 512 + lane;
#pragma unroll
        for (int nt = 0; nt < 16; nt++) {
            uint4 bf = wrow[nt * 32];
            mma16816(acc[nt][0], acc[nt][1], acc[nt][2], acc[nt][3],
                     ah0, ah1, ah2, ah3, bf.x, bf.y,
                     acc[nt][0], acc[nt][1], acc[nt][2], acc[nt][3]);
            mma16816(acc[nt][0], acc[nt][1], acc[nt][2], acc[nt][3],
                     al0, al1, al2, al3, bf.x, bf.y,
                     acc[nt][0], acc[nt][1], acc[nt][2], acc[nt][3]);
            mma16816(acc[nt][0], acc[nt][1], acc[nt][2], acc[nt][3],
                     ah0, ah1, ah2, ah3, bf.z, bf.w,
                     acc[nt][0], acc[nt][1], acc[nt][2], acc[nt][3]);
        }
    }

    if (do_scores) {
        vs0 += __shfl_xor_sync(0xffffffffu, vs0, 1);
        vs0 += __shfl_xor_sync(0xffffffffu, vs0, 2);
        vd0 += __shfl_xor_sync(0xffffffffu, vd0, 1);
        vd0 += __shfl_xor_sync(0xffffffffu, vd0, 2);
        vs1 += __shfl_xor_sync(0xffffffffu, vs1, 1);
        vs1 += __shfl_xor_sync(0xffffffffu, vs1, 2);
        vd1 += __shfl_xor_sync(0xffffffffu, vd1, 1);
        vd1 += __shfl_xor_sync(0xffffffffu, vd1, 2);
        if (qq == 0) {
            float ba = g_bass[l], bd = g_bads[l];
            if (row0 < NN) { g_ssrc[row0] = vs0 + ba; g_sdst[row0] = vd0 + bd; }
            if (row0 + 8 < NN) { g_ssrc[row0 + 8] = vs1 + ba; g_sdst[row0 + 8] = vd1 + bd; }
        }
    }

    const bool st0 = (row0 < NN);
    const bool st1 = (row0 + 8 < NN);
#pragma unroll
    for (int nt = 0; nt < 16; nt++) {
        float2 bb = *reinterpret_cast<const float2*>(sBias + nt * 8 + qq * 2);
        float o0 = acc[nt][0] + bb.x, o1 = acc[nt][1] + bb.y;
        float o2 = acc[nt][2] + bb.x, o3 = acc[nt][3] + bb.y;
        if (do_relu) {
            o0 = fmaxf(o0, 0.f); o1 = fmaxf(o1, 0.f);
            o2 = fmaxf(o2, 0.f); o3 = fmaxf(o3, 0.f);
        }
        if (c_sel == 0) {
            if (st0)
                *reinterpret_cast<float2*>(g_ha + (size_t)row0 * HH + nt * 8 + qq * 2) =
                    make_float2(o0, o1);
            if (st1)
                *reinterpret_cast<float2*>(g_ha + (size_t)(row0 + 8) * HH + nt * 8 + qq * 2) =
                    make_float2(o2, o3);
        } else {
            if (st0)
                *reinterpret_cast<__half2*>(g_msgh + (size_t)row0 * HH + nt * 8 + qq * 2) =
                    __floats2half2_rn(o0, o1);
            if (st1)
                *reinterpret_cast<__half2*>(g_msgh + (size_t)(row0 + 8) * HH + nt * 8 + qq * 2) =
                    __floats2half2_rn(o2, o3);
        }
    }
}

// ---------------- fp32 GEMM for input projection (K=64, runs once) ----------------
__global__ __launch_bounds__(256, 2) void k_gemm(const float* __restrict__ A,
                                                 const float* __restrict__ W,
                                                 const float* __restrict__ bias,
                                                 int nrows, int K) {
    float* C = g_ha;
    __shared__ __align__(16) float As[128][33];
    __shared__ __align__(16) float Ws[32][128];

    int tid = threadIdx.x;
    int bm = blockIdx.x * 128;
    int tx = tid & 15;
    int ty = tid >> 4;
    int n0 = tx * 8;
    int m0 = ty * 8;

    float acc[8][8];
#pragma unroll
    for (int i = 0; i < 8; i++)
#pragma unroll
        for (int j = 0; j < 8; j++) acc[i][j] = 0.f;

    int nch = K >> 5;
    for (int ch = 0; ch < nch; ch++) {
        int k0 = ch * 32;
#pragma unroll
        for (int i = 0; i < 4; i++) {
            int idx = tid + i * 256;
            int m = idx >> 3;
            int kq = (idx & 7) * 4;
            float4 v = make_float4(0.f, 0.f, 0.f, 0.f);
            int gr = bm + m;
            if (gr < nrows)
                v = *reinterpret_cast<const float4*>(A + (size_t)gr * K + k0 + kq);
            As[m][kq] = v.x; As[m][kq + 1] = v.y; As[m][kq + 2] = v.z; As[m][kq + 3] = v.w;
        }
#pragma unroll
        for (int i = 0; i < 4; i++) {
            int idx = tid + i * 256;
            int n = idx >> 3;
            int kq = (idx & 7) * 4;
            float4 v = *reinterpret_cast<const float4*>(W + (size_t)n * K + k0 + kq);
            Ws[kq][n] = v.x; Ws[kq + 1][n] = v.y; Ws[kq + 2][n] = v.z; Ws[kq + 3][n] = v.w;
        }
        __syncthreads();
#pragma unroll 8
        for (int kk = 0; kk < 32; kk++) {
            float a[8];
#pragma unroll
            for (int i = 0; i < 8; i++) a[i] = As[m0 + i][kk];
            float4 b0 = *reinterpret_cast<const float4*>(&Ws[kk][n0]);
            float4 b1 = *reinterpret_cast<const float4*>(&Ws[kk][n0 + 4]);
#pragma unroll
            for (int i = 0; i < 8; i++) {
                acc[i][0] = fmaf(a[i], b0.x, acc[i][0]);
                acc[i][1] = fmaf(a[i], b0.y, acc[i][1]);
                acc[i][2] = fmaf(a[i], b0.z, acc[i][2]);
                acc[i][3] = fmaf(a[i], b0.w, acc[i][3]);
                acc[i][4] = fmaf(a[i], b1.x, acc[i][4]);
                acc[i][5] = fmaf(a[i], b1.y, acc[i][5]);
                acc[i][6] = fmaf(a[i], b1.z, acc[i][6]);
                acc[i][7] = fmaf(a[i], b1.w, acc[i][7]);
            }
        }
        __syncthreads();
    }

    float4 bv0 = *reinterpret_cast<const float4*>(bias + n0);
    float4 bv1 = *reinterpret_cast<const float4*>(bias + n0 + 4);
#pragma unroll
    for (int i = 0; i < 8; i++) {
        int gr = bm + m0 + i;
        if (gr >= nrows) continue;
        float4 o0, o1;
        o0.x = fmaxf(acc[i][0] + bv0.x, 0.f); o0.y = fmaxf(acc[i][1] + bv0.y, 0.f);
        o0.z = fmaxf(acc[i][2] + bv0.z, 0.f); o0.w = fmaxf(acc[i][3] + bv0.w, 0.f);
        o1.x = fmaxf(acc[i][4] + bv1.x, 0.f); o1.y = fmaxf(acc[i][5] + bv1.y, 0.f);
        o1.z = fmaxf(acc[i][6] + bv1.z, 0.f); o1.w = fmaxf(acc[i][7] + bv1.w, 0.f);
        float* cp = C + (size_t)gr * HH + n0;
        *reinterpret_cast<float4*>(cp) = o0;
        *reinterpret_cast<float4*>(cp + 4) = o1;
    }
}

// ---------------- gather-aggregate: warp per destination node over CSR ----------------
// msg rows are fp16 (256B): each lane covers 4 columns (lane*4 .. lane*4+3) = 8 bytes.
__global__ void k_agg(int l) {
    int gw = (blockIdx.x * blockDim.x + threadIdx.x) >> 5;
    int lane = threadIdx.x & 31;
    if (gw >= NN) return;
    int n = gw;
    int beg = g_rowptr[n];
    int end = g_rowptr[n + 1];
    float sdn = g_sdst[n];
    const float* __restrict__ sb = g_sb + (size_t)l * EE;
    const __half2* __restrict__ msg2 = reinterpret_cast<const __half2*>(g_msgh);
    float4 acc = make_float4(0.f, 0.f, 0.f, 0.f);
    int p = beg;
    for (; p + 1 < end; p += 2) {
        int s0 = g_srcp[p];
        int s1 = g_srcp[p + 1];
        float x0 = g_ssrc[s0] + sdn + sb[p];
        float x1 = g_ssrc[s1] + sdn + sb[p + 1];
        float gt0 = g_ewp[p] / (1.f + __expf(-x0));
        float gt1 = g_ewp[p + 1] / (1.f + __expf(-x1));
        __half2 m0a = msg2[(size_t)s0 * 64 + lane * 2];
        __half2 m0b = msg2[(size_t)s0 * 64 + lane * 2 + 1];
        __half2 m1a = msg2[(size_t)s1 * 64 + lane * 2];
        __half2 m1b = msg2[(size_t)s1 * 64 + lane * 2 + 1];
        float2 f0a = __half22float2(m0a), f0b = __half22float2(m0b);
        float2 f1a = __half22float2(m1a), f1b = __half22float2(m1b);
        acc.x = fmaf(f0a.x, gt0, acc.x); acc.y = fmaf(f0a.y, gt0, acc.y);
        acc.z = fmaf(f0b.x, gt0, acc.z); acc.w = fmaf(f0b.y, gt0, acc.w);
        acc.x = fmaf(f1a.x, gt1, acc.x); acc.y = fmaf(f1a.y, gt1, acc.y);
        acc.z = fmaf(f1b.x, gt1, acc.z); acc.w = fmaf(f1b.y, gt1, acc.w);
    }
    if (p < end) {
        int s0 = g_srcp[p];
        float x0 = g_ssrc[s0] + sdn + sb[p];
        float gt0 = g_ewp[p] / (1.f + __expf(-x0));
        __half2 m0a = msg2[(size_t)s0 * 64 + lane * 2];
        __half2 m0b = msg2[(size_t)s0 * 64 + lane * 2 + 1];
        float2 f0a = __half22float2(m0a), f0b = __half22float2(m0b);
        acc.x = fmaf(f0a.x, gt0, acc.x); acc.y = fmaf(f0a.y, gt0, acc.y);
        acc.z = fmaf(f0b.x, gt0, acc.z); acc.w = fmaf(f0b.y, gt0, acc.w);
    }
    float4 h4 = reinterpret_cast<const float4*>(g_ha)[(size_t)n * 32 + lane];
    float4 o;
    o.x = h4.x + acc.x; o.y = h4.y + acc.y; o.z = h4.z + acc.z; o.w = h4.w + acc.w;
    reinterpret_cast<float4*>(g_a2)[(size_t)n * 32 + lane] = o;
}

// ---------------- graph readout ----------------
__global__ void k_grep() {
    int c = threadIdx.x & 127;
    int half = threadIdx.x >> 7;
    int rs = blockIdx.x * 196;
    int re = rs + 196;
    if (re > NN) re = NN;
    float acc = 0.f;
    for (int r = rs + half; r < re; r += 2) acc += g_ha[(size_t)r * HH + c];
    __shared__ float sr[256];
    sr[threadIdx.x] = acc;
    __syncthreads();
    if (threadIdx.x < 128)
        g_gpart[blockIdx.x * HH + threadIdx.x] = sr[threadIdx.x] + sr[threadIdx.x + 128];
}

__global__ void k_final(const float* __restrict__ W_out, const float* __restrict__ b_out,
                        float* __restrict__ out) {
    int t = threadIdx.x;  // 128 threads
    float s = 0.f;
    for (int b = 0; b < 256; b++) s += g_gpart[b * HH + t];
    float v = s * (1.f / (float)NN) * W_out[t];
    __shared__ float r[128];
    r[t] = v;
    __syncthreads();
    for (int off = 64; off; off >>= 1) {
        if (t < off) r[t] += r[t + off];
        __syncthreads();
    }
    if (t == 0) out[0] = (r[0] + b_out[0]) * (1.f / 50.f);
}

// ---------------- launch ----------------
extern "C" void kernel_launch(void* const* d_in, const int* in_sizes, int n_in,
                              void* d_out, int out_size) {
    const float* x      = (const float*)d_in[0];
    const int*   ei     = (const int*)d_in[1];
    const float* ew     = (const float*)d_in[2];
    const float* ea     = (const float*)d_in[3];
    const float* W_in   = (const float*)d_in[4];
    const float* b_in   = (const float*)d_in[5];
    const float* W_e1   = (const float*)d_in[6];
    const float* b_e1   = (const float*)d_in[7];
    const float* W_e2   = (const float*)d_in[8];
    const float* b_e2   = (const float*)d_in[9];
    const float* W_as   = (const float*)d_in[10];
    const float* b_as   = (const float*)d_in[11];
    const float* W_ad   = (const float*)d_in[12];
    const float* b_ad   = (const float*)d_in[13];
    const float* W_m    = (const float*)d_in[14];
    const float* b_m    = (const float*)d_in[15];
    const float* W_r    = (const float*)d_in[16];
    const float* b_r    = (const float*)d_in[17];
    const float* W_out  = (const float*)d_in[18];
    const float* b_out  = (const float*)d_in[19];
    float* out = (float*)d_out;

    cudaFuncSetAttribute(k_sbias_tc, cudaFuncAttributeMaxDynamicSharedMemorySize, SBT_SMEM);
    cudaFuncSetAttribute(k_gemm_tc, cudaFuncAttributeMaxDynamicSharedMemorySize, GT_SMEM);

    const int gridE = (EE + 255) / 256;   // 6250
    const int gridN = (NN + 255) / 256;   // 196
    const int gridG = (NN + 127) / 128;   // 391

    k_init<<<gridN, 256>>>();
    k_prep<<<LL, HH>>>(W_e1, b_e1, W_e2, b_e2, W_as, b_as, W_ad, b_ad);
    k_prepB<<<LL * 16, 32>>>();
    k_prepW<<<12 * 128, 32>>>(W_m, W_r);
    k_hist<<<gridE, 256>>>(ei);
    k_scanA<<<49, 1024>>>();
    k_scanB<<<1, 32>>>();
    k_scanC<<<49, 1024>>>();
    k_scatter<<<gridE, 256>>>(ei, ew);
    // input projection: ha = relu(x @ W_in^T + b_in)
    k_gemm<<<gridG, 256>>>(x, W_in, b_in, NN, DIN);
    // per-edge bias for all 6 layers (CSR order), tensor cores via mma.sync
    k_sbias_tc<<<625, 256, SBT_SMEM>>>(ea);

    for (int l = 0; l < LL; l++) {
        // msg = ha @ W_m^T + b_m  (fp16 out, + fused s_src/s_dst scores)
        k_gemm_tc<<<gridG, 256, GT_SMEM>>>(1, l * 2 + 0, b_m + l * HH, 1, 0, 1, l);
        // a2 = ha + segment_sum(msg[src] * gate)
        k_agg<<<gridE, 256>>>(l);
        // ha = relu(a2 @ W_r^T + b_r)
        k_gemm_tc<<<gridG, 256, GT_SMEM>>>(2, l * 2 + 1, b_r + l * HH, 0, 1, 0, l);
    }

    k_grep<<<256, 256>>>();
    k_final<<<1, 128>>>(W_out, b_out, out);
}